// round 9
// baseline (speedup 1.0000x reference)
#include <cuda_runtime.h>
#include <cuda_bf16.h>
#include <math.h>
#include <stdint.h>

// Problem constants
#define BB 2
#define LL 2048
#define DD 2048
#define HH 16
#define HD 128
#define MROWS (BB * LL)        // 4096
#define D3 (3 * DD)            // 6144
#define D8 (8 * DD)            // 16384
#define D4 (4 * DD)            // 8192

// ---------------- scratch ----------------
__device__ float g_qkv[(size_t)MROWS * D3];
__device__ float g_s  [(size_t)BB * HH * LL * LL];
__device__ float g_x1 [(size_t)MROWS * DD];
__device__ float g_cos[LL * 64];
__device__ float g_sin[LL * 64];

// A-side split activations (DD-wide: rmsnorm out, attn-o out)
__device__ __align__(16) __nv_bfloat16 g_ah[(size_t)MROWS * DD];
__device__ __align__(16) __nv_bfloat16 g_al[(size_t)MROWS * DD];
// FFN hidden split (D4-wide, output of fused Wp+SwiGLU)
__device__ __align__(16) __nv_bfloat16 g_fh[(size_t)MROWS * D4];
__device__ __align__(16) __nv_bfloat16 g_fl[(size_t)MROWS * D4];

__device__ __align__(16) __nv_bfloat16 g_qh[(size_t)BB * HH * LL * HD];
__device__ __align__(16) __nv_bfloat16 g_ql[(size_t)BB * HH * LL * HD];
__device__ __align__(16) __nv_bfloat16 g_kh[(size_t)BB * HH * LL * HD];
__device__ __align__(16) __nv_bfloat16 g_kl[(size_t)BB * HH * LL * HD];
__device__ __align__(16) __nv_bfloat16 g_vth[(size_t)BB * HH * HD * LL];
__device__ __align__(16) __nv_bfloat16 g_vtl[(size_t)BB * HH * HD * LL];
__device__ __align__(16) __nv_bfloat16 g_ph[(size_t)BB * HH * LL * LL];
__device__ __align__(16) __nv_bfloat16 g_pl[(size_t)BB * HH * LL * LL];

__device__ __align__(16) __nv_bfloat16 g_WqkvT_hi[(size_t)D3 * DD];
__device__ __align__(16) __nv_bfloat16 g_WqkvT_lo[(size_t)D3 * DD];
__device__ __align__(16) __nv_bfloat16 g_WoT_hi[(size_t)DD * DD];
__device__ __align__(16) __nv_bfloat16 g_WoT_lo[(size_t)DD * DD];
__device__ __align__(16) __nv_bfloat16 g_WpT_hi[(size_t)D8 * DD];
__device__ __align__(16) __nv_bfloat16 g_WpT_lo[(size_t)D8 * DD];
__device__ __align__(16) __nv_bfloat16 g_WffT_hi[(size_t)DD * D4];
__device__ __align__(16) __nv_bfloat16 g_WffT_lo[(size_t)DD * D4];

// ================= helpers =================
__device__ __forceinline__ uint32_t smem_u32(const void* p) {
    uint32_t a;
    asm("{ .reg .u64 t; cvta.to.shared.u64 t, %1; cvt.u32.u64 %0, t; }" : "=r"(a) : "l"(p));
    return a;
}

#define CP_ASYNC16(dst, src) \
    asm volatile("cp.async.cg.shared.global [%0], [%1], 16;" :: "r"(dst), "l"(src) : "memory")
#define CP_COMMIT() asm volatile("cp.async.commit_group;" ::: "memory")
#define CP_WAIT1()  asm volatile("cp.async.wait_group 1;" ::: "memory")

#define LDSM4(r, addr) \
    asm volatile("ldmatrix.sync.aligned.m8n8.x4.shared.b16 {%0,%1,%2,%3}, [%4];" \
        : "=r"((r)[0]), "=r"((r)[1]), "=r"((r)[2]), "=r"((r)[3]) : "r"(addr))

#define MMA_BF16(d, a, b0, b1) \
    asm volatile("mma.sync.aligned.m16n8k16.row.col.f32.bf16.bf16.f32 " \
        "{%0,%1,%2,%3}, {%4,%5,%6,%7}, {%8,%9}, {%0,%1,%2,%3};" \
        : "+f"((d)[0]), "+f"((d)[1]), "+f"((d)[2]), "+f"((d)[3]) \
        : "r"((a)[0]), "r"((a)[1]), "r"((a)[2]), "r"((a)[3]), "r"(b0), "r"(b1))

// ================= RoPE tables =================
__global__ void rope_table_kernel() {
    int p = blockIdx.x, i = threadIdx.x;
    double inv_freq = pow(10000.0, -(double)(2 * i) / (double)HD);
    double ang = (double)p * inv_freq;
    g_cos[p * 64 + i] = (float)cos(ang);
    g_sin[p * 64 + i] = (float)sin(ang);
}

// ================= RMSNorm -> split bf16 hi/lo =================
__global__ void rmsnorm_split_kernel(const float* __restrict__ x,
                                     const float* __restrict__ g,
                                     __nv_bfloat16* __restrict__ hi,
                                     __nv_bfloat16* __restrict__ lo) {
    int row = blockIdx.x;
    const float* xr = x + (size_t)row * DD;
    float ss = 0.f;
    for (int c = threadIdx.x * 4; c < DD; c += blockDim.x * 4) {
        float4 v = *(const float4*)(xr + c);
        ss += v.x * v.x + v.y * v.y + v.z * v.z + v.w * v.w;
    }
    __shared__ float red[256];
    red[threadIdx.x] = ss;
    __syncthreads();
    for (int s = blockDim.x / 2; s > 0; s >>= 1) {
        if (threadIdx.x < s) red[threadIdx.x] += red[threadIdx.x + s];
        __syncthreads();
    }
    float scale = rsqrtf(red[0] / (float)DD + 1e-8f);
    for (int c = threadIdx.x * 4; c < DD; c += blockDim.x * 4) {
        float4 v = *(const float4*)(xr + c);
        float4 gv = *(const float4*)(g + c);
        float y[4] = {v.x * scale * gv.x, v.y * scale * gv.y,
                      v.z * scale * gv.z, v.w * scale * gv.w};
#pragma unroll
        for (int j = 0; j < 4; j++) {
            __nv_bfloat16 h = __float2bfloat16(y[j]);
            hi[(size_t)row * DD + c + j] = h;
            lo[(size_t)row * DD + c + j] = __float2bfloat16(y[j] - __bfloat162float(h));
        }
    }
}

// ================= weight transpose + split =================
__global__ void transpose_split_kernel(const float* __restrict__ W,
                                       __nv_bfloat16* __restrict__ Thi,
                                       __nv_bfloat16* __restrict__ Tlo,
                                       int K, int N) {
    __shared__ float t[32][33];
    int n0 = blockIdx.x * 32, k0 = blockIdx.y * 32;
    int tx = threadIdx.x, ty = threadIdx.y;
#pragma unroll
    for (int r = 0; r < 4; r++) {
        int k = ty + r * 8;
        t[k][tx] = W[(size_t)(k0 + k) * N + n0 + tx];
    }
    __syncthreads();
#pragma unroll
    for (int r = 0; r < 4; r++) {
        int n = ty + r * 8;
        float v = t[tx][n];
        __nv_bfloat16 h = __float2bfloat16(v);
        Thi[(size_t)(n0 + n) * K + k0 + tx] = h;
        Tlo[(size_t)(n0 + n) * K + k0 + tx] = __float2bfloat16(v - __bfloat162float(h));
    }
}

// Wp transpose with gate/value column interleave: out row 2i=gate_i, 2i+1=value_i
__global__ void transpose_split_interleave_kernel(const float* __restrict__ W,
                                                  __nv_bfloat16* __restrict__ Thi,
                                                  __nv_bfloat16* __restrict__ Tlo,
                                                  int K, int N) {
    __shared__ float t[32][33];
    int n0 = blockIdx.x * 32, k0 = blockIdx.y * 32;
    int tx = threadIdx.x, ty = threadIdx.y;
#pragma unroll
    for (int r = 0; r < 4; r++) {
        int k = ty + r * 8;
        t[k][tx] = W[(size_t)(k0 + k) * N + n0 + tx];
    }
    __syncthreads();
#pragma unroll
    for (int r = 0; r < 4; r++) {
        int n = ty + r * 8;
        int ncol = n0 + n;
        int rout = ((ncol & (D4 - 1)) << 1) | (ncol >> 13);   // N = 16384
        float v = t[tx][n];
        __nv_bfloat16 h = __float2bfloat16(v);
        Thi[(size_t)rout * K + k0 + tx] = h;
        Tlo[(size_t)rout * K + k0 + tx] = __float2bfloat16(v - __bfloat162float(h));
    }
}

// ====== mma.sync bf16x3 GEMM: 128x128 tile, 256 threads, 3-stage, 2 CTAs/SM ======
// SWIGLU=true: B cols interleaved (gate,value); epilogue writes silu(gate)*value
// split-bf16 into Oh/Ol [M, N/2]. Else fp32 C = acc + bias (+R).
#define TM 128
#define TN 128
#define KC 32
#define AHI_OFF 0
#define ALO_OFF 8192
#define BHI_OFF 16384
#define BLO_OFF 24576
#define STG_BYTES 32768
#define GEMM_SMEM (3 * STG_BYTES)

template <bool SWIGLU>
__global__ void __launch_bounds__(256, 2) gemm_mma3_kernel(
    const __nv_bfloat16* __restrict__ Ahi, const __nv_bfloat16* __restrict__ Alo,
    const __nv_bfloat16* __restrict__ Bhi, const __nv_bfloat16* __restrict__ Blo,
    const float* __restrict__ bias, const float* __restrict__ R,
    float* __restrict__ C,
    __nv_bfloat16* __restrict__ Oh, __nv_bfloat16* __restrict__ Ol,
    int M, int N, int K)
{
    extern __shared__ char sm[];
    const int tid = threadIdx.x;
    const int lane = tid & 31;
    const int wid = tid >> 5;
    const int wm = wid & 3;
    const int wn = wid >> 2;
    const int bm = blockIdx.x * TM;
    const int bn = blockIdx.y * TN;
    const uint32_t smb = smem_u32(sm);

    const int rowA_base = wm * 32 + (lane & 15);
    const int rowB_base = wn * 64 + (lane & 7) + ((lane >> 4) << 3);
    const uint32_t xorw = (uint32_t)((lane & 6) << 3);

    float acc[2][8][4];
#pragma unroll
    for (int i = 0; i < 2; i++)
#pragma unroll
        for (int j = 0; j < 8; j++)
#pragma unroll
            for (int q = 0; q < 4; q++) acc[i][j][q] = 0.f;

    auto issue_chunk = [&](int k0, int stg) {
        const uint32_t sbase = smb + stg * STG_BYTES;
#pragma unroll
        for (int i = 0; i < 8; i++) {
            int u = tid + (i << 8);
            const __nv_bfloat16* src;
            uint32_t roff;
            int row;
            if (u < 512)       { row = u >> 2;          src = Ahi + (size_t)(bm + row) * K; roff = AHI_OFF; }
            else if (u < 1024) { row = (u - 512) >> 2;  src = Alo + (size_t)(bm + row) * K; roff = ALO_OFF; }
            else if (u < 1536) { row = (u - 1024) >> 2; src = Bhi + (size_t)(bn + row) * K; roff = BHI_OFF; }
            else               { row = (u - 1536) >> 2; src = Blo + (size_t)(bn + row) * K; roff = BLO_OFF; }
            int seg = u & 3;
            uint32_t dst = sbase + roff + (uint32_t)(row * 64) +
                           (((uint32_t)(seg * 16)) ^ ((uint32_t)((row & 6) << 3)));
            CP_ASYNC16(dst, src + k0 + seg * 8);
        }
        CP_COMMIT();
    };

    const int NC = K / KC;
    issue_chunk(0, 0);
    issue_chunk(KC, 1);

    for (int c = 0; c < NC; ++c) {
        CP_WAIT1();
        __syncthreads();
        if (c + 2 < NC) issue_chunk((c + 2) * KC, (c + 2) % 3);
        else CP_COMMIT();

        const uint32_t stg = smb + (uint32_t)((c % 3) * STG_BYTES);

#pragma unroll
        for (int kk = 0; kk < 2; kk++) {
            const uint32_t cbA = ((uint32_t)(kk * 32 + ((lane >> 4) << 4))) ^ xorw;
            const uint32_t cbB = ((uint32_t)(kk * 32 + (((lane >> 3) & 1) << 4))) ^ xorw;

            uint32_t ah[2][4], bh4[4][4], fa[2][4], fb[4][4];
#pragma unroll
            for (int mt = 0; mt < 2; mt++)
                LDSM4(ah[mt], stg + AHI_OFF + (uint32_t)((rowA_base + mt * 16) * 64) + cbA);
#pragma unroll
            for (int bt = 0; bt < 4; bt++)
                LDSM4(bh4[bt], stg + BHI_OFF + (uint32_t)((rowB_base + bt * 16) * 64) + cbB);
#pragma unroll
            for (int bt = 0; bt < 4; bt++)
                LDSM4(fb[bt], stg + BLO_OFF + (uint32_t)((rowB_base + bt * 16) * 64) + cbB);
            // hi x hi
#pragma unroll
            for (int mt = 0; mt < 2; mt++)
#pragma unroll
                for (int nt = 0; nt < 8; nt++) {
                    const uint32_t* b = bh4[nt >> 1];
                    if (nt & 1) MMA_BF16(acc[mt][nt], ah[mt], b[2], b[3]);
                    else        MMA_BF16(acc[mt][nt], ah[mt], b[0], b[1]);
                }
            // hi x lo
#pragma unroll
            for (int mt = 0; mt < 2; mt++)
#pragma unroll
                for (int nt = 0; nt < 8; nt++) {
                    const uint32_t* b = fb[nt >> 1];
                    if (nt & 1) MMA_BF16(acc[mt][nt], ah[mt], b[2], b[3]);
                    else        MMA_BF16(acc[mt][nt], ah[mt], b[0], b[1]);
                }
            // lo x hi
#pragma unroll
            for (int mt = 0; mt < 2; mt++)
                LDSM4(fa[mt], stg + ALO_OFF + (uint32_t)((rowA_base + mt * 16) * 64) + cbA);
#pragma unroll
            for (int mt = 0; mt < 2; mt++)
#pragma unroll
                for (int nt = 0; nt < 8; nt++) {
                    const uint32_t* b = bh4[nt >> 1];
                    if (nt & 1) MMA_BF16(acc[mt][nt], fa[mt], b[2], b[3]);
                    else        MMA_BF16(acc[mt][nt], fa[mt], b[0], b[1]);
                }
        }
    }

    // ---- epilogue ----
    if (SWIGLU) {
        const int outN = N >> 1;   // 8192
#pragma unroll
        for (int mt = 0; mt < 2; mt++) {
            const int m = bm + wm * 32 + mt * 16 + (lane >> 2);
#pragma unroll
            for (int nt = 0; nt < 8; nt++) {
                const int nperm = bn + wn * 64 + nt * 8 + ((lane & 3) << 1);
                const int i = nperm >> 1;
                float bg = bias[i];
                float bv = bias[outN + i];
                float g0 = acc[mt][nt][0] + bg, v0 = acc[mt][nt][1] + bv;
                float g1 = acc[mt][nt][2] + bg, v1 = acc[mt][nt][3] + bv;
                float r0 = g0 / (1.f + expf(-g0)) * v0;
                float r1 = g1 / (1.f + expf(-g1)) * v1;
                __nv_bfloat16 h0 = __float2bfloat16(r0);
                __nv_bfloat16 h1 = __float2bfloat16(r1);
                Oh[(size_t)m * outN + i] = h0;
                Ol[(size_t)m * outN + i] = __float2bfloat16(r0 - __bfloat162float(h0));
                Oh[(size_t)(m + 8) * outN + i] = h1;
                Ol[(size_t)(m + 8) * outN + i] = __float2bfloat16(r1 - __bfloat162float(h1));
            }
        }
    } else {
#pragma unroll
        for (int mt = 0; mt < 2; mt++) {
            const int m = bm + wm * 32 + mt * 16 + (lane >> 2);
#pragma unroll
            for (int nt = 0; nt < 8; nt++) {
                const int n = bn + wn * 64 + nt * 8 + ((lane & 3) << 1);
                float2 b2 = *(const float2*)(bias + n);
                float2 o0, o1;
                o0.x = acc[mt][nt][0] + b2.x;
                o0.y = acc[mt][nt][1] + b2.y;
                o1.x = acc[mt][nt][2] + b2.x;
                o1.y = acc[mt][nt][3] + b2.y;
                if (R) {
                    float2 r0 = *(const float2*)(R + (size_t)m * N + n);
                    float2 r1 = *(const float2*)(R + (size_t)(m + 8) * N + n);
                    o0.x += r0.x; o0.y += r0.y;
                    o1.x += r1.x; o1.y += r1.y;
                }
                *(float2*)(C + (size_t)m * N + n) = o0;
                *(float2*)(C + (size_t)(m + 8) * N + n) = o1;
            }
        }
    }
}

// ================= RoPE: qkv fp32 -> split bf16 q,k in [B,H,L,HD] =================
__global__ void rope_apply_split_kernel() {
    int idx = blockIdx.x * blockDim.x + threadIdx.x;
    if (idx >= BB * LL * HH * 64) return;
    int d = idx & 63;
    int h = (idx >> 6) & (HH - 1);
    int bl = idx >> 10;
    int b = bl >> 11;
    int l = bl & (LL - 1);
    float c = g_cos[l * 64 + d];
    float s = g_sin[l * 64 + d];
    size_t src = (size_t)bl * D3 + h * HD + d;
    size_t dst = ((size_t)(b * HH + h) * LL + l) * HD + d;

    float q1 = g_qkv[src], q2 = g_qkv[src + 64];
    float qa = q1 * c - q2 * s;
    float qb = q2 * c + q1 * s;
    __nv_bfloat16 t;
    t = __float2bfloat16(qa); g_qh[dst] = t;      g_ql[dst] = __float2bfloat16(qa - __bfloat162float(t));
    t = __float2bfloat16(qb); g_qh[dst + 64] = t; g_ql[dst + 64] = __float2bfloat16(qb - __bfloat162float(t));

    size_t ks = src + DD;
    float k1 = g_qkv[ks], k2 = g_qkv[ks + 64];
    float ka = k1 * c - k2 * s;
    float kb = k2 * c + k1 * s;
    t = __float2bfloat16(ka); g_kh[dst] = t;      g_kl[dst] = __float2bfloat16(ka - __bfloat162float(t));
    t = __float2bfloat16(kb); g_kh[dst + 64] = t; g_kl[dst + 64] = __float2bfloat16(kb - __bfloat162float(t));
}

// ================= V transpose + split =================
__global__ void v_transpose_split_kernel() {
    __shared__ float t[32][33];
    int l0 = blockIdx.x * 32, d0 = blockIdx.y * 32, bh = blockIdx.z;
    int b = bh >> 4, h = bh & 15;
    int tx = threadIdx.x, ty = threadIdx.y;
#pragma unroll
    for (int r = 0; r < 4; r++) {
        int l = ty + r * 8;
        t[l][tx] = g_qkv[(size_t)(b * LL + l0 + l) * D3 + 2 * DD + h * HD + d0 + tx];
    }
    __syncthreads();
#pragma unroll
    for (int r = 0; r < 4; r++) {
        int d = ty + r * 8;
        float v = t[tx][d];
        __nv_bfloat16 hv = __float2bfloat16(v);
        size_t dst = ((size_t)bh * HD + d0 + d) * LL + l0 + tx;
        g_vth[dst] = hv;
        g_vtl[dst] = __float2bfloat16(v - __bfloat162float(hv));
    }
}

// ================= attention scores (bf16x3 MMA, 3-stage, 2 CTAs/SM) =================
#define ATT_STG 32768
#define ATT_SMEM (3 * ATT_STG)

__global__ void __launch_bounds__(256, 2) attn_scores_mma_kernel() {
    extern __shared__ char sm[];
    const int jb = blockIdx.x, ib = blockIdx.y, bh = blockIdx.z;
    if (jb > ib) return;
    const int tid = threadIdx.x, lane = tid & 31, wid = tid >> 5;
    const int wm = wid & 3, wn = wid >> 2;
    const uint32_t smb = smem_u32(sm);

    const __nv_bfloat16* Qh = g_qh + ((size_t)bh * LL + ib * 128) * HD;
    const __nv_bfloat16* Ql = g_ql + ((size_t)bh * LL + ib * 128) * HD;
    const __nv_bfloat16* Kh = g_kh + ((size_t)bh * LL + jb * 128) * HD;
    const __nv_bfloat16* Kl = g_kl + ((size_t)bh * LL + jb * 128) * HD;

    const int rowA_base = wm * 32 + (lane & 15);
    const int rowB_base = wn * 64 + (lane & 7) + ((lane >> 4) << 3);
    const uint32_t xorw = (uint32_t)((lane & 6) << 3);

    float acc[2][8][4];
#pragma unroll
    for (int i = 0; i < 2; i++)
#pragma unroll
        for (int j = 0; j < 8; j++)
#pragma unroll
            for (int q = 0; q < 4; q++) acc[i][j][q] = 0.f;

    auto issue = [&](int c, int stg) {
        const uint32_t sb = smb + (uint32_t)(stg * ATT_STG);
        const int k0 = c * 32;
#pragma unroll
        for (int i = 0; i < 8; i++) {
            int u = tid + (i << 8);
            int row = (u >> 2) & 127;
            int seg = u & 3;
            const __nv_bfloat16* src = (u < 512) ? Qh : (u < 1024) ? Ql : (u < 1536) ? Kh : Kl;
            uint32_t roff = (uint32_t)(u >> 9) * 8192;
            uint32_t dst = sb + roff + (uint32_t)(row * 64) +
                           (((uint32_t)(seg * 16)) ^ ((uint32_t)((row & 6) << 3)));
            CP_ASYNC16(dst, src + (size_t)row * HD + k0 + seg * 8);
        }
        CP_COMMIT();
    };

    issue(0, 0);
    issue(1, 1);
#pragma unroll 1
    for (int c = 0; c < 4; c++) {
        CP_WAIT1();
        __syncthreads();
        if (c + 2 < 4) issue(c + 2, (c + 2) % 3);
        else CP_COMMIT();
        const uint32_t stg = smb + (uint32_t)((c % 3) * ATT_STG);
#pragma unroll
        for (int kk = 0; kk < 2; kk++) {
            const uint32_t cbA = ((uint32_t)(kk * 32 + ((lane >> 4) << 4))) ^ xorw;
            const uint32_t cbB = ((uint32_t)(kk * 32 + (((lane >> 3) & 1) << 4))) ^ xorw;
            uint32_t ah[2][4], bh4[4][4], fb[4][4], fa[2][4];
#pragma unroll
            for (int mt = 0; mt < 2; mt++)
                LDSM4(ah[mt], stg + 0 + (uint32_t)((rowA_base + mt * 16) * 64) + cbA);
#pragma unroll
            for (int bt = 0; bt < 4; bt++)
                LDSM4(bh4[bt], stg + 16384 + (uint32_t)((rowB_base + bt * 16) * 64) + cbB);
#pragma unroll
            for (int bt = 0; bt < 4; bt++)
                LDSM4(fb[bt], stg + 24576 + (uint32_t)((rowB_base + bt * 16) * 64) + cbB);
#pragma unroll
            for (int mt = 0; mt < 2; mt++)
#pragma unroll
                for (int nt = 0; nt < 8; nt++) {
                    const uint32_t* b = bh4[nt >> 1];
                    if (nt & 1) MMA_BF16(acc[mt][nt], ah[mt], b[2], b[3]);
                    else        MMA_BF16(acc[mt][nt], ah[mt], b[0], b[1]);
                }
#pragma unroll
            for (int mt = 0; mt < 2; mt++)
#pragma unroll
                for (int nt = 0; nt < 8; nt++) {
                    const uint32_t* b = fb[nt >> 1];
                    if (nt & 1) MMA_BF16(acc[mt][nt], ah[mt], b[2], b[3]);
                    else        MMA_BF16(acc[mt][nt], ah[mt], b[0], b[1]);
                }
#pragma unroll
            for (int mt = 0; mt < 2; mt++)
                LDSM4(fa[mt], stg + 8192 + (uint32_t)((rowA_base + mt * 16) * 64) + cbA);
#pragma unroll
            for (int mt = 0; mt < 2; mt++)
#pragma unroll
                for (int nt = 0; nt < 8; nt++) {
                    const uint32_t* b = bh4[nt >> 1];
                    if (nt & 1) MMA_BF16(acc[mt][nt], fa[mt], b[2], b[3]);
                    else        MMA_BF16(acc[mt][nt], fa[mt], b[0], b[1]);
                }
        }
    }

    const float scale = 0.08838834764831845f;
#pragma unroll
    for (int mt = 0; mt < 2; mt++) {
        const int i0 = ib * 128 + wm * 32 + mt * 16 + (lane >> 2);
#pragma unroll
        for (int nt = 0; nt < 8; nt++) {
            const int j0 = jb * 128 + wn * 64 + nt * 8 + ((lane & 3) << 1);
            float2 o0, o1;
            o0.x = (j0     <= i0)     ? acc[mt][nt][0] * scale : -1e30f;
            o0.y = (j0 + 1 <= i0)     ? acc[mt][nt][1] * scale : -1e30f;
            o1.x = (j0     <= i0 + 8) ? acc[mt][nt][2] * scale : -1e30f;
            o1.y = (j0 + 1 <= i0 + 8) ? acc[mt][nt][3] * scale : -1e30f;
            *(float2*)(g_s + ((size_t)bh * LL + i0) * LL + j0) = o0;
            *(float2*)(g_s + ((size_t)bh * LL + i0 + 8) * LL + j0) = o1;
        }
    }
}

// ========== row softmax -> split bf16 P (no fp32 writeback; exp recompute) ==========
__global__ void softmax_kernel() {
    int r = blockIdx.x;
    int i = r & (LL - 1);
    int len = ((i >> 6) + 1) << 6;
    int len2 = ((i >> 7) + 1) << 7;
    const float* p = g_s + (size_t)r * LL;
    __nv_bfloat16* ph = g_ph + (size_t)r * LL;
    __nv_bfloat16* pl = g_pl + (size_t)r * LL;
    __shared__ float red[128];

    float m = -1e30f;
    for (int c = threadIdx.x * 4; c < len; c += 512) {
        float4 v = *(const float4*)(p + c);
        m = fmaxf(m, fmaxf(fmaxf(v.x, v.y), fmaxf(v.z, v.w)));
    }
    red[threadIdx.x] = m;
    __syncthreads();
    for (int s = 64; s > 0; s >>= 1) {
        if (threadIdx.x < s) red[threadIdx.x] = fmaxf(red[threadIdx.x], red[threadIdx.x + s]);
        __syncthreads();
    }
    m = red[0];
    __syncthreads();

    float sum = 0.f;
    for (int c = threadIdx.x * 4; c < len; c += 512) {
        float4 v = *(const float4*)(p + c);
        sum += expf(v.x - m) + expf(v.y - m) + expf(v.z - m) + expf(v.w - m);
    }
    red[threadIdx.x] = sum;
    __syncthreads();
    for (int s = 64; s > 0; s >>= 1) {
        if (threadIdx.x < s) red[threadIdx.x] += red[threadIdx.x + s];
        __syncthreads();
    }
    float inv = 1.f / red[0];
    for (int c = threadIdx.x * 4; c < len; c += 512) {
        float4 v = *(const float4*)(p + c);
        float y[4] = {expf(v.x - m) * inv, expf(v.y - m) * inv,
                      expf(v.z - m) * inv, expf(v.w - m) * inv};
        __nv_bfloat16 h0 = __float2bfloat16(y[0]), h1 = __float2bfloat16(y[1]);
        __nv_bfloat16 h2 = __float2bfloat16(y[2]), h3 = __float2bfloat16(y[3]);
        *(__nv_bfloat162*)(ph + c) = __halves2bfloat162(h0, h1);
        *(__nv_bfloat162*)(ph + c + 2) = __halves2bfloat162(h2, h3);
        *(__nv_bfloat162*)(pl + c) = __halves2bfloat162(
            __float2bfloat16(y[0] - __bfloat162float(h0)),
            __float2bfloat16(y[1] - __bfloat162float(h1)));
        *(__nv_bfloat162*)(pl + c + 2) = __halves2bfloat162(
            __float2bfloat16(y[2] - __bfloat162float(h2)),
            __float2bfloat16(y[3] - __bfloat162float(h3)));
    }
    __nv_bfloat162 z = __halves2bfloat162(__float2bfloat16(0.f), __float2bfloat16(0.f));
    for (int c = len + threadIdx.x * 4; c < len2; c += 512) {
        *(__nv_bfloat162*)(ph + c) = z;
        *(__nv_bfloat162*)(ph + c + 2) = z;
        *(__nv_bfloat162*)(pl + c) = z;
        *(__nv_bfloat162*)(pl + c + 2) = z;
    }
}

// ================= O = P @ V (bf16x3 MMA, 3-stage, 2 CTAs/SM) -> split o =================
__global__ void __launch_bounds__(256, 2) attn_pv_mma_kernel() {
    extern __shared__ char sm[];
    const int ib = blockIdx.x, bh = blockIdx.y;
    const int b = bh >> 4, h = bh & 15;
    const int tid = threadIdx.x, lane = tid & 31, wid = tid >> 5;
    const int wm = wid & 3, wn = wid >> 2;
    const uint32_t smb = smem_u32(sm);

    const __nv_bfloat16* Ph = g_ph + ((size_t)bh * LL + ib * 128) * LL;
    const __nv_bfloat16* Pl = g_pl + ((size_t)bh * LL + ib * 128) * LL;
    const __nv_bfloat16* Vh = g_vth + (size_t)bh * HD * LL;
    const __nv_bfloat16* Vl = g_vtl + (size_t)bh * HD * LL;

    const int rowA_base = wm * 32 + (lane & 15);
    const int rowB_base = wn * 64 + (lane & 7) + ((lane >> 4) << 3);
    const uint32_t xorw = (uint32_t)((lane & 6) << 3);

    float acc[2][8][4];
#pragma unroll
    for (int i = 0; i < 2; i++)
#pragma unroll
        for (int j = 0; j < 8; j++)
#pragma unroll
            for (int q = 0; q < 4; q++) acc[i][j][q] = 0.f;

    auto issue = [&](int c, int stg) {
        const uint32_t sb = smb + (uint32_t)(stg * ATT_STG);
        const int j0 = c * 32;
#pragma unroll
        for (int i = 0; i < 8; i++) {
            int u = tid + (i << 8);
            int row = (u >> 2) & 127;
            int seg = u & 3;
            const __nv_bfloat16* src = (u < 512) ? Ph : (u < 1024) ? Pl : (u < 1536) ? Vh : Vl;
            uint32_t roff = (uint32_t)(u >> 9) * 8192;
            uint32_t dst = sb + roff + (uint32_t)(row * 64) +
                           (((uint32_t)(seg * 16)) ^ ((uint32_t)((row & 6) << 3)));
            CP_ASYNC16(dst, src + (size_t)row * LL + j0 + seg * 8);
        }
        CP_COMMIT();
    };

    const int NC = (ib + 1) * 4;
    issue(0, 0);
    issue(1, 1);
#pragma unroll 1
    for (int c = 0; c < NC; c++) {
        CP_WAIT1();
        __syncthreads();
        if (c + 2 < NC) issue(c + 2, (c + 2) % 3);
        else CP_COMMIT();
        const uint32_t stg = smb + (uint32_t)((c % 3) * ATT_STG);
#pragma unroll
        for (int kk = 0; kk < 2; kk++) {
            const uint32_t cbA = ((uint32_t)(kk * 32 + ((lane >> 4) << 4))) ^ xorw;
            const uint32_t cbB = ((uint32_t)(kk * 32 + (((lane >> 3) & 1) << 4))) ^ xorw;
            uint32_t ah[2][4], bh4[4][4], fb[4][4], fa[2][4];
#pragma unroll
            for (int mt = 0; mt < 2; mt++)
                LDSM4(ah[mt], stg + 0 + (uint32_t)((rowA_base + mt * 16) * 64) + cbA);
#pragma unroll
            for (int bt = 0; bt < 4; bt++)
                LDSM4(bh4[bt], stg + 16384 + (uint32_t)((rowB_base + bt * 16) * 64) + cbB);
#pragma unroll
            for (int bt = 0; bt < 4; bt++)
                LDSM4(fb[bt], stg + 24576 + (uint32_t)((rowB_base + bt * 16) * 64) + cbB);
#pragma unroll
            for (int mt = 0; mt < 2; mt++)
#pragma unroll
                for (int nt = 0; nt < 8; nt++) {
                    const uint32_t* bb = bh4[nt >> 1];
                    if (nt & 1) MMA_BF16(acc[mt][nt], ah[mt], bb[2], bb[3]);
                    else        MMA_BF16(acc[mt][nt], ah[mt], bb[0], bb[1]);
                }
#pragma unroll
            for (int mt = 0; mt < 2; mt++)
#pragma unroll
                for (int nt = 0; nt < 8; nt++) {
                    const uint32_t* bb = fb[nt >> 1];
                    if (nt & 1) MMA_BF16(acc[mt][nt], ah[mt], bb[2], bb[3]);
                    else        MMA_BF16(acc[mt][nt], ah[mt], bb[0], bb[1]);
                }
#pragma unroll
            for (int mt = 0; mt < 2; mt++)
                LDSM4(fa[mt], stg + 8192 + (uint32_t)((rowA_base + mt * 16) * 64) + cbA);
#pragma unroll
            for (int mt = 0; mt < 2; mt++)
#pragma unroll
                for (int nt = 0; nt < 8; nt++) {
                    const uint32_t* bb = bh4[nt >> 1];
                    if (nt & 1) MMA_BF16(acc[mt][nt], fa[mt], bb[2], bb[3]);
                    else        MMA_BF16(acc[mt][nt], fa[mt], bb[0], bb[1]);
                }
        }
    }

#pragma unroll
    for (int mt = 0; mt < 2; mt++) {
        const int qi = ib * 128 + wm * 32 + mt * 16 + (lane >> 2);
#pragma unroll
        for (int nt = 0; nt < 8; nt++) {
            const int d = wn * 64 + nt * 8 + ((lane & 3) << 1);
            size_t base0 = (size_t)(b * LL + qi) * DD + h * HD + d;
            size_t base1 = (size_t)(b * LL + qi + 8) * DD + h * HD + d;
            float v0 = acc[mt][nt][0], v1 = acc[mt][nt][1];
            float v2 = acc[mt][nt][2], v3 = acc[mt][nt][3];
            __nv_bfloat16 h0 = __float2bfloat16(v0), h1 = __float2bfloat16(v1);
            __nv_bfloat16 h2 = __float2bfloat16(v2), h3 = __float2bfloat16(v3);
            *(__nv_bfloat162*)(g_ah + base0) = __halves2bfloat162(h0, h1);
            *(__nv_bfloat162*)(g_ah + base1) = __halves2bfloat162(h2, h3);
            *(__nv_bfloat162*)(g_al + base0) = __halves2bfloat162(
                __float2bfloat16(v0 - __bfloat162float(h0)),
                __float2bfloat16(v1 - __bfloat162float(h1)));
            *(__nv_bfloat162*)(g_al + base1) = __halves2bfloat162(
                __float2bfloat16(v2 - __bfloat162float(h2)),
                __float2bfloat16(v3 - __bfloat162float(h3)));
        }
    }
}

// ================= launch =================
extern "C" void kernel_launch(void* const* d_in, const int* in_sizes, int n_in,
                              void* d_out, int out_size) {
    const float* x    = (const float*)d_in[0];
    const float* Wqkv = (const float*)d_in[1];
    const float* bqkv = (const float*)d_in[2];
    const float* Wo   = (const float*)d_in[3];
    const float* bo   = (const float*)d_in[4];
    const float* g1   = (const float*)d_in[5];
    const float* g2   = (const float*)d_in[6];
    const float* Wp   = (const float*)d_in[7];
    const float* bp   = (const float*)d_in[8];
    const float* Wff  = (const float*)d_in[9];
    const float* bff  = (const float*)d_in[10];
    float* out = (float*)d_out;

    __nv_bfloat16 *ah, *al, *fh, *fl, *wqh, *wql, *woh, *wol, *wph, *wpl, *wfh, *wfl;
    float *qkv, *x1;
    cudaGetSymbolAddress((void**)&ah,  g_ah);
    cudaGetSymbolAddress((void**)&al,  g_al);
    cudaGetSymbolAddress((void**)&fh,  g_fh);
    cudaGetSymbolAddress((void**)&fl,  g_fl);
    cudaGetSymbolAddress((void**)&wqh, g_WqkvT_hi);
    cudaGetSymbolAddress((void**)&wql, g_WqkvT_lo);
    cudaGetSymbolAddress((void**)&woh, g_WoT_hi);
    cudaGetSymbolAddress((void**)&wol, g_WoT_lo);
    cudaGetSymbolAddress((void**)&wph, g_WpT_hi);
    cudaGetSymbolAddress((void**)&wpl, g_WpT_lo);
    cudaGetSymbolAddress((void**)&wfh, g_WffT_hi);
    cudaGetSymbolAddress((void**)&wfl, g_WffT_lo);
    cudaGetSymbolAddress((void**)&qkv, g_qkv);
    cudaGetSymbolAddress((void**)&x1,  g_x1);

    cudaFuncSetAttribute(gemm_mma3_kernel<false>,
                         cudaFuncAttributeMaxDynamicSharedMemorySize, GEMM_SMEM);
    cudaFuncSetAttribute(gemm_mma3_kernel<true>,
                         cudaFuncAttributeMaxDynamicSharedMemorySize, GEMM_SMEM);
    cudaFuncSetAttribute(attn_scores_mma_kernel,
                         cudaFuncAttributeMaxDynamicSharedMemorySize, ATT_SMEM);
    cudaFuncSetAttribute(attn_pv_mma_kernel,
                         cudaFuncAttributeMaxDynamicSharedMemorySize, ATT_SMEM);

    dim3 tb(32, 8);

    // ---- side stream: all weight transposes, forked from main stream ----
    cudaStream_t s2;
    cudaStreamCreate(&s2);
    cudaEvent_t eF, eWq, eWo, eWp, eWf;
    cudaEventCreateWithFlags(&eF,  cudaEventDisableTiming);
    cudaEventCreateWithFlags(&eWq, cudaEventDisableTiming);
    cudaEventCreateWithFlags(&eWo, cudaEventDisableTiming);
    cudaEventCreateWithFlags(&eWp, cudaEventDisableTiming);
    cudaEventCreateWithFlags(&eWf, cudaEventDisableTiming);

    cudaEventRecord(eF, 0);
    cudaStreamWaitEvent(s2, eF, 0);
    transpose_split_kernel<<<dim3(D3 / 32, DD / 32), tb, 0, s2>>>(Wqkv, wqh, wql, DD, D3);
    cudaEventRecord(eWq, s2);
    transpose_split_kernel<<<dim3(DD / 32, DD / 32), tb, 0, s2>>>(Wo, woh, wol, DD, DD);
    cudaEventRecord(eWo, s2);
    transpose_split_interleave_kernel<<<dim3(D8 / 32, DD / 32), tb, 0, s2>>>(Wp, wph, wpl, DD, D8);
    cudaEventRecord(eWp, s2);
    transpose_split_kernel<<<dim3(DD / 32, D4 / 32), tb, 0, s2>>>(Wff, wfh, wfl, D4, DD);
    cudaEventRecord(eWf, s2);

    // ---- main stream ----
    rope_table_kernel<<<LL, 64>>>();
    rmsnorm_split_kernel<<<MROWS, 256>>>(x, g1, ah, al);

    cudaStreamWaitEvent(0, eWq, 0);
    gemm_mma3_kernel<false><<<dim3(MROWS / TM, D3 / TN), 256, GEMM_SMEM>>>(
        ah, al, wqh, wql, bqkv, nullptr, qkv, nullptr, nullptr, MROWS, D3, DD);

    {
        int total = BB * LL * HH * 64;
        rope_apply_split_kernel<<<(total + 255) / 256, 256>>>();
    }
    v_transpose_split_kernel<<<dim3(LL / 32, HD / 32, BB * HH), tb>>>();
    attn_scores_mma_kernel<<<dim3(LL / 128, LL / 128, BB * HH), 256, ATT_SMEM>>>();
    softmax_kernel<<<BB * HH * LL, 128>>>();
    attn_pv_mma_kernel<<<dim3(LL / 128, BB * HH), 256, ATT_SMEM>>>();

    cudaStreamWaitEvent(0, eWo, 0);
    gemm_mma3_kernel<false><<<dim3(MROWS / TM, DD / TN), 256, GEMM_SMEM>>>(
        ah, al, woh, wol, bo, x, x1, nullptr, nullptr, MROWS, DD, DD);

    rmsnorm_split_kernel<<<MROWS, 256>>>(x1, g2, ah, al);

    cudaStreamWaitEvent(0, eWp, 0);
    // fused Wp GEMM + SwiGLU: writes split bf16 hidden into g_fh/g_fl
    gemm_mma3_kernel<true><<<dim3(MROWS / TM, D8 / TN), 256, GEMM_SMEM>>>(
        ah, al, wph, wpl, bp, nullptr, nullptr, fh, fl, MROWS, D8, DD);

    cudaStreamWaitEvent(0, eWf, 0);
    gemm_mma3_kernel<false><<<dim3(MROWS / TM, DD / TN), 256, GEMM_SMEM>>>(
        fh, fl, wfh, wfl, bff, x1, out, nullptr, nullptr, MROWS, DD, D4);
}

// round 10
// speedup vs baseline: 1.4518x; 1.4518x over previous
#include <cuda_runtime.h>
#include <cuda_fp16.h>
#include <math.h>
#include <stdint.h>

// Problem constants
#define BB 2
#define LL 2048
#define DD 2048
#define HH 16
#define HD 128
#define MROWS (BB * LL)        // 4096
#define D3 (3 * DD)            // 6144
#define D8 (8 * DD)            // 16384
#define D4 (4 * DD)            // 8192

// ---------------- scratch ----------------
__device__ float g_qkv[(size_t)MROWS * D3];
__device__ float g_s  [(size_t)BB * HH * LL * LL];
__device__ float g_x1 [(size_t)MROWS * DD];
__device__ float g_cos[LL * 64];
__device__ float g_sin[LL * 64];

// A-side split activations (fp16 hi/lo)
__device__ __align__(16) __half g_ah[(size_t)MROWS * DD];
__device__ __align__(16) __half g_al[(size_t)MROWS * DD];
__device__ __align__(16) __half g_fh[(size_t)MROWS * D4];
__device__ __align__(16) __half g_fl[(size_t)MROWS * D4];

__device__ __align__(16) __half g_qh[(size_t)BB * HH * LL * HD];
__device__ __align__(16) __half g_ql[(size_t)BB * HH * LL * HD];
__device__ __align__(16) __half g_kh[(size_t)BB * HH * LL * HD];   // K single
__device__ __align__(16) __half g_vth[(size_t)BB * HH * HD * LL];  // V^T single
__device__ __align__(16) __half g_ph[(size_t)BB * HH * LL * LL];
__device__ __align__(16) __half g_pl[(size_t)BB * HH * LL * LL];

// single-fp16 transposed weights [N,K]
__device__ __align__(16) __half g_WqkvT[(size_t)D3 * DD];
__device__ __align__(16) __half g_WoT[(size_t)DD * DD];
__device__ __align__(16) __half g_WpT[(size_t)D8 * DD];
__device__ __align__(16) __half g_WffT[(size_t)DD * D4];

// ================= helpers =================
__device__ __forceinline__ uint32_t smem_u32(const void* p) {
    uint32_t a;
    asm("{ .reg .u64 t; cvta.to.shared.u64 t, %1; cvt.u32.u64 %0, t; }" : "=r"(a) : "l"(p));
    return a;
}

#define CP_ASYNC16(dst, src) \
    asm volatile("cp.async.cg.shared.global [%0], [%1], 16;" :: "r"(dst), "l"(src) : "memory")
#define CP_COMMIT() asm volatile("cp.async.commit_group;" ::: "memory")
#define CP_WAIT1()  asm volatile("cp.async.wait_group 1;" ::: "memory")

#define LDSM4(r, addr) \
    asm volatile("ldmatrix.sync.aligned.m8n8.x4.shared.b16 {%0,%1,%2,%3}, [%4];" \
        : "=r"((r)[0]), "=r"((r)[1]), "=r"((r)[2]), "=r"((r)[3]) : "r"(addr))

#define MMA_F16(d, a, b0, b1) \
    asm volatile("mma.sync.aligned.m16n8k16.row.col.f32.f16.f16.f32 " \
        "{%0,%1,%2,%3}, {%4,%5,%6,%7}, {%8,%9}, {%0,%1,%2,%3};" \
        : "+f"((d)[0]), "+f"((d)[1]), "+f"((d)[2]), "+f"((d)[3]) \
        : "r"((a)[0]), "r"((a)[1]), "r"((a)[2]), "r"((a)[3]), "r"(b0), "r"(b1))

// ================= RoPE tables =================
__global__ void rope_table_kernel() {
    int p = blockIdx.x, i = threadIdx.x;
    double inv_freq = pow(10000.0, -(double)(2 * i) / (double)HD);
    double ang = (double)p * inv_freq;
    g_cos[p * 64 + i] = (float)cos(ang);
    g_sin[p * 64 + i] = (float)sin(ang);
}

// ================= RMSNorm -> split fp16 hi/lo =================
__global__ void rmsnorm_split_kernel(const float* __restrict__ x,
                                     const float* __restrict__ g,
                                     __half* __restrict__ hi,
                                     __half* __restrict__ lo) {
    int row = blockIdx.x;
    const float* xr = x + (size_t)row * DD;
    float ss = 0.f;
    for (int c = threadIdx.x * 4; c < DD; c += blockDim.x * 4) {
        float4 v = *(const float4*)(xr + c);
        ss += v.x * v.x + v.y * v.y + v.z * v.z + v.w * v.w;
    }
    __shared__ float red[256];
    red[threadIdx.x] = ss;
    __syncthreads();
    for (int s = blockDim.x / 2; s > 0; s >>= 1) {
        if (threadIdx.x < s) red[threadIdx.x] += red[threadIdx.x + s];
        __syncthreads();
    }
    float scale = rsqrtf(red[0] / (float)DD + 1e-8f);
    for (int c = threadIdx.x * 4; c < DD; c += blockDim.x * 4) {
        float4 v = *(const float4*)(xr + c);
        float4 gv = *(const float4*)(g + c);
        float y[4] = {v.x * scale * gv.x, v.y * scale * gv.y,
                      v.z * scale * gv.z, v.w * scale * gv.w};
#pragma unroll
        for (int j = 0; j < 4; j++) {
            __half h = __float2half_rn(y[j]);
            hi[(size_t)row * DD + c + j] = h;
            lo[(size_t)row * DD + c + j] = __float2half_rn(y[j] - __half2float(h));
        }
    }
}

// ================= weight transpose -> single fp16 =================
__global__ void transpose_half_kernel(const float* __restrict__ W,
                                      __half* __restrict__ T,
                                      int K, int N) {
    __shared__ float t[32][33];
    int n0 = blockIdx.x * 32, k0 = blockIdx.y * 32;
    int tx = threadIdx.x, ty = threadIdx.y;
#pragma unroll
    for (int r = 0; r < 4; r++) {
        int k = ty + r * 8;
        t[k][tx] = W[(size_t)(k0 + k) * N + n0 + tx];
    }
    __syncthreads();
#pragma unroll
    for (int r = 0; r < 4; r++) {
        int n = ty + r * 8;
        T[(size_t)(n0 + n) * K + k0 + tx] = __float2half_rn(t[tx][n]);
    }
}

// Wp transpose with gate/value interleave: out row 2i=gate_i, 2i+1=value_i
__global__ void transpose_half_interleave_kernel(const float* __restrict__ W,
                                                 __half* __restrict__ T,
                                                 int K, int N) {
    __shared__ float t[32][33];
    int n0 = blockIdx.x * 32, k0 = blockIdx.y * 32;
    int tx = threadIdx.x, ty = threadIdx.y;
#pragma unroll
    for (int r = 0; r < 4; r++) {
        int k = ty + r * 8;
        t[k][tx] = W[(size_t)(k0 + k) * N + n0 + tx];
    }
    __syncthreads();
#pragma unroll
    for (int r = 0; r < 4; r++) {
        int n = ty + r * 8;
        int ncol = n0 + n;
        int rout = ((ncol & (D4 - 1)) << 1) | (ncol >> 13);   // N = 16384
        T[(size_t)rout * K + k0 + tx] = __float2half_rn(t[tx][n]);
    }
}

// ====== fp16x2 GEMM: C = (Ahi+Alo)[M,K] @ B[N,K]^T; 128x128, 256 thr, 3-stage ======
#define TM 128
#define TN 128
#define KC 32
#define AHI_OFF 0
#define ALO_OFF 8192
#define B_OFF 16384
#define STG_BYTES 24576
#define GEMM_SMEM (3 * STG_BYTES)

template <bool SWIGLU>
__global__ void __launch_bounds__(256, 2) gemm_f16x2_kernel(
    const __half* __restrict__ Ahi, const __half* __restrict__ Alo,
    const __half* __restrict__ B,
    const float* __restrict__ bias, const float* __restrict__ R,
    float* __restrict__ C,
    __half* __restrict__ Oh, __half* __restrict__ Ol,
    int M, int N, int K)
{
    extern __shared__ char sm[];
    const int tid = threadIdx.x;
    const int lane = tid & 31;
    const int wid = tid >> 5;
    const int wm = wid & 3;
    const int wn = wid >> 2;
    const int bm = blockIdx.x * TM;
    const int bn = blockIdx.y * TN;
    const uint32_t smb = smem_u32(sm);

    const int rowA_base = wm * 32 + (lane & 15);
    const int rowB_base = wn * 64 + (lane & 7) + ((lane >> 4) << 3);
    const uint32_t xorw = (uint32_t)((lane & 6) << 3);

    float acc[2][8][4];
#pragma unroll
    for (int i = 0; i < 2; i++)
#pragma unroll
        for (int j = 0; j < 8; j++)
#pragma unroll
            for (int q = 0; q < 4; q++) acc[i][j][q] = 0.f;

    // 1536 x 16B per chunk, 6 per thread
    auto issue_chunk = [&](int k0, int stg) {
        const uint32_t sbase = smb + stg * STG_BYTES;
#pragma unroll
        for (int i = 0; i < 6; i++) {
            int u = tid + (i << 8);
            const __half* src;
            uint32_t roff;
            int row;
            if (u < 512)       { row = u >> 2;          src = Ahi + (size_t)(bm + row) * K; roff = AHI_OFF; }
            else if (u < 1024) { row = (u - 512) >> 2;  src = Alo + (size_t)(bm + row) * K; roff = ALO_OFF; }
            else               { row = (u - 1024) >> 2; src = B + (size_t)(bn + row) * K;   roff = B_OFF; }
            int seg = u & 3;
            uint32_t dst = sbase + roff + (uint32_t)(row * 64) +
                           (((uint32_t)(seg * 16)) ^ ((uint32_t)((row & 6) << 3)));
            CP_ASYNC16(dst, src + k0 + seg * 8);
        }
        CP_COMMIT();
    };

    const int NC = K / KC;
    issue_chunk(0, 0);
    issue_chunk(KC, 1);

    for (int c = 0; c < NC; ++c) {
        CP_WAIT1();
        __syncthreads();
        if (c + 2 < NC) issue_chunk((c + 2) * KC, (c + 2) % 3);
        else CP_COMMIT();

        const uint32_t stg = smb + (uint32_t)((c % 3) * STG_BYTES);

#pragma unroll
        for (int kk = 0; kk < 2; kk++) {
            const uint32_t cbA = ((uint32_t)(kk * 32 + ((lane >> 4) << 4))) ^ xorw;
            const uint32_t cbB = ((uint32_t)(kk * 32 + (((lane >> 3) & 1) << 4))) ^ xorw;

            uint32_t ah[2][4], b4[4][4], fa[2][4];
#pragma unroll
            for (int mt = 0; mt < 2; mt++)
                LDSM4(ah[mt], stg + AHI_OFF + (uint32_t)((rowA_base + mt * 16) * 64) + cbA);
#pragma unroll
            for (int bt = 0; bt < 4; bt++)
                LDSM4(b4[bt], stg + B_OFF + (uint32_t)((rowB_base + bt * 16) * 64) + cbB);
#pragma unroll
            for (int mt = 0; mt < 2; mt++)
                LDSM4(fa[mt], stg + ALO_OFF + (uint32_t)((rowA_base + mt * 16) * 64) + cbA);
            // hi x B
#pragma unroll
            for (int mt = 0; mt < 2; mt++)
#pragma unroll
                for (int nt = 0; nt < 8; nt++) {
                    const uint32_t* b = b4[nt >> 1];
                    if (nt & 1) MMA_F16(acc[mt][nt], ah[mt], b[2], b[3]);
                    else        MMA_F16(acc[mt][nt], ah[mt], b[0], b[1]);
                }
            // lo x B
#pragma unroll
            for (int mt = 0; mt < 2; mt++)
#pragma unroll
                for (int nt = 0; nt < 8; nt++) {
                    const uint32_t* b = b4[nt >> 1];
                    if (nt & 1) MMA_F16(acc[mt][nt], fa[mt], b[2], b[3]);
                    else        MMA_F16(acc[mt][nt], fa[mt], b[0], b[1]);
                }
        }
    }

    // ---- epilogue ----
    if (SWIGLU) {
        const int outN = N >> 1;
#pragma unroll
        for (int mt = 0; mt < 2; mt++) {
            const int m = bm + wm * 32 + mt * 16 + (lane >> 2);
#pragma unroll
            for (int nt = 0; nt < 8; nt++) {
                const int nperm = bn + wn * 64 + nt * 8 + ((lane & 3) << 1);
                const int i = nperm >> 1;
                float bg = bias[i];
                float bv = bias[outN + i];
                float g0 = acc[mt][nt][0] + bg, v0 = acc[mt][nt][1] + bv;
                float g1 = acc[mt][nt][2] + bg, v1 = acc[mt][nt][3] + bv;
                float r0 = g0 / (1.f + expf(-g0)) * v0;
                float r1 = g1 / (1.f + expf(-g1)) * v1;
                __half h0 = __float2half_rn(r0);
                __half h1 = __float2half_rn(r1);
                Oh[(size_t)m * outN + i] = h0;
                Ol[(size_t)m * outN + i] = __float2half_rn(r0 - __half2float(h0));
                Oh[(size_t)(m + 8) * outN + i] = h1;
                Ol[(size_t)(m + 8) * outN + i] = __float2half_rn(r1 - __half2float(h1));
            }
        }
    } else {
#pragma unroll
        for (int mt = 0; mt < 2; mt++) {
            const int m = bm + wm * 32 + mt * 16 + (lane >> 2);
#pragma unroll
            for (int nt = 0; nt < 8; nt++) {
                const int n = bn + wn * 64 + nt * 8 + ((lane & 3) << 1);
                float2 b2 = *(const float2*)(bias + n);
                float2 o0, o1;
                o0.x = acc[mt][nt][0] + b2.x;
                o0.y = acc[mt][nt][1] + b2.y;
                o1.x = acc[mt][nt][2] + b2.x;
                o1.y = acc[mt][nt][3] + b2.y;
                if (R) {
                    float2 r0 = *(const float2*)(R + (size_t)m * N + n);
                    float2 r1 = *(const float2*)(R + (size_t)(m + 8) * N + n);
                    o0.x += r0.x; o0.y += r0.y;
                    o1.x += r1.x; o1.y += r1.y;
                }
                *(float2*)(C + (size_t)m * N + n) = o0;
                *(float2*)(C + (size_t)(m + 8) * N + n) = o1;
            }
        }
    }
}

// ================= RoPE: qkv fp32 -> fp16 q(split), k(single) in [B,H,L,HD] =================
__global__ void rope_apply_split_kernel() {
    int idx = blockIdx.x * blockDim.x + threadIdx.x;
    if (idx >= BB * LL * HH * 64) return;
    int d = idx & 63;
    int h = (idx >> 6) & (HH - 1);
    int bl = idx >> 10;
    int b = bl >> 11;
    int l = bl & (LL - 1);
    float c = g_cos[l * 64 + d];
    float s = g_sin[l * 64 + d];
    size_t src = (size_t)bl * D3 + h * HD + d;
    size_t dst = ((size_t)(b * HH + h) * LL + l) * HD + d;

    float q1 = g_qkv[src], q2 = g_qkv[src + 64];
    float qa = q1 * c - q2 * s;
    float qb = q2 * c + q1 * s;
    __half t;
    t = __float2half_rn(qa); g_qh[dst] = t;      g_ql[dst] = __float2half_rn(qa - __half2float(t));
    t = __float2half_rn(qb); g_qh[dst + 64] = t; g_ql[dst + 64] = __float2half_rn(qb - __half2float(t));

    size_t ks = src + DD;
    float k1 = g_qkv[ks], k2 = g_qkv[ks + 64];
    g_kh[dst]      = __float2half_rn(k1 * c - k2 * s);
    g_kh[dst + 64] = __float2half_rn(k2 * c + k1 * s);
}

// ================= V transpose -> single fp16 [B,H,HD,L] =================
__global__ void v_transpose_kernel() {
    __shared__ float t[32][33];
    int l0 = blockIdx.x * 32, d0 = blockIdx.y * 32, bh = blockIdx.z;
    int b = bh >> 4, h = bh & 15;
    int tx = threadIdx.x, ty = threadIdx.y;
#pragma unroll
    for (int r = 0; r < 4; r++) {
        int l = ty + r * 8;
        t[l][tx] = g_qkv[(size_t)(b * LL + l0 + l) * D3 + 2 * DD + h * HD + d0 + tx];
    }
    __syncthreads();
#pragma unroll
    for (int r = 0; r < 4; r++) {
        int d = ty + r * 8;
        g_vth[((size_t)bh * HD + d0 + d) * LL + l0 + tx] = __float2half_rn(t[tx][d]);
    }
}

// ================= attention scores (fp16x2: Q split, K single) =================
#define ATT_STG 24576
#define ATT_SMEM (3 * ATT_STG)

__global__ void __launch_bounds__(256, 2) attn_scores_mma_kernel() {
    extern __shared__ char sm[];
    const int jb = blockIdx.x, ib = blockIdx.y, bh = blockIdx.z;
    if (jb > ib) return;
    const int tid = threadIdx.x, lane = tid & 31, wid = tid >> 5;
    const int wm = wid & 3, wn = wid >> 2;
    const uint32_t smb = smem_u32(sm);

    const __half* Qh = g_qh + ((size_t)bh * LL + ib * 128) * HD;
    const __half* Ql = g_ql + ((size_t)bh * LL + ib * 128) * HD;
    const __half* Kh = g_kh + ((size_t)bh * LL + jb * 128) * HD;

    const int rowA_base = wm * 32 + (lane & 15);
    const int rowB_base = wn * 64 + (lane & 7) + ((lane >> 4) << 3);
    const uint32_t xorw = (uint32_t)((lane & 6) << 3);

    float acc[2][8][4];
#pragma unroll
    for (int i = 0; i < 2; i++)
#pragma unroll
        for (int j = 0; j < 8; j++)
#pragma unroll
            for (int q = 0; q < 4; q++) acc[i][j][q] = 0.f;

    auto issue = [&](int c, int stg) {
        const uint32_t sb = smb + (uint32_t)(stg * ATT_STG);
        const int k0 = c * 32;
#pragma unroll
        for (int i = 0; i < 6; i++) {
            int u = tid + (i << 8);
            int row = (u >> 2) & 127;
            int seg = u & 3;
            const __half* src = (u < 512) ? Qh : (u < 1024) ? Ql : Kh;
            uint32_t roff = (uint32_t)(u >> 9) * 8192;
            uint32_t dst = sb + roff + (uint32_t)(row * 64) +
                           (((uint32_t)(seg * 16)) ^ ((uint32_t)((row & 6) << 3)));
            CP_ASYNC16(dst, src + (size_t)row * HD + k0 + seg * 8);
        }
        CP_COMMIT();
    };

    issue(0, 0);
    issue(1, 1);
#pragma unroll 1
    for (int c = 0; c < 4; c++) {
        CP_WAIT1();
        __syncthreads();
        if (c + 2 < 4) issue(c + 2, (c + 2) % 3);
        else CP_COMMIT();
        const uint32_t stg = smb + (uint32_t)((c % 3) * ATT_STG);
#pragma unroll
        for (int kk = 0; kk < 2; kk++) {
            const uint32_t cbA = ((uint32_t)(kk * 32 + ((lane >> 4) << 4))) ^ xorw;
            const uint32_t cbB = ((uint32_t)(kk * 32 + (((lane >> 3) & 1) << 4))) ^ xorw;
            uint32_t ah[2][4], b4[4][4], fa[2][4];
#pragma unroll
            for (int mt = 0; mt < 2; mt++)
                LDSM4(ah[mt], stg + 0 + (uint32_t)((rowA_base + mt * 16) * 64) + cbA);
#pragma unroll
            for (int bt = 0; bt < 4; bt++)
                LDSM4(b4[bt], stg + 16384 + (uint32_t)((rowB_base + bt * 16) * 64) + cbB);
#pragma unroll
            for (int mt = 0; mt < 2; mt++)
                LDSM4(fa[mt], stg + 8192 + (uint32_t)((rowA_base + mt * 16) * 64) + cbA);
#pragma unroll
            for (int mt = 0; mt < 2; mt++)
#pragma unroll
                for (int nt = 0; nt < 8; nt++) {
                    const uint32_t* b = b4[nt >> 1];
                    if (nt & 1) MMA_F16(acc[mt][nt], ah[mt], b[2], b[3]);
                    else        MMA_F16(acc[mt][nt], ah[mt], b[0], b[1]);
                }
#pragma unroll
            for (int mt = 0; mt < 2; mt++)
#pragma unroll
                for (int nt = 0; nt < 8; nt++) {
                    const uint32_t* b = b4[nt >> 1];
                    if (nt & 1) MMA_F16(acc[mt][nt], fa[mt], b[2], b[3]);
                    else        MMA_F16(acc[mt][nt], fa[mt], b[0], b[1]);
                }
        }
    }

    const float scale = 0.08838834764831845f;
#pragma unroll
    for (int mt = 0; mt < 2; mt++) {
        const int i0 = ib * 128 + wm * 32 + mt * 16 + (lane >> 2);
#pragma unroll
        for (int nt = 0; nt < 8; nt++) {
            const int j0 = jb * 128 + wn * 64 + nt * 8 + ((lane & 3) << 1);
            float2 o0, o1;
            o0.x = (j0     <= i0)     ? acc[mt][nt][0] * scale : -1e30f;
            o0.y = (j0 + 1 <= i0)     ? acc[mt][nt][1] * scale : -1e30f;
            o1.x = (j0     <= i0 + 8) ? acc[mt][nt][2] * scale : -1e30f;
            o1.y = (j0 + 1 <= i0 + 8) ? acc[mt][nt][3] * scale : -1e30f;
            *(float2*)(g_s + ((size_t)bh * LL + i0) * LL + j0) = o0;
            *(float2*)(g_s + ((size_t)bh * LL + i0 + 8) * LL + j0) = o1;
        }
    }
}

// ========== row softmax -> split fp16 P ==========
__global__ void softmax_kernel() {
    int r = blockIdx.x;
    int i = r & (LL - 1);
    int len = ((i >> 6) + 1) << 6;
    int len2 = ((i >> 7) + 1) << 7;
    const float* p = g_s + (size_t)r * LL;
    __half* ph = g_ph + (size_t)r * LL;
    __half* pl = g_pl + (size_t)r * LL;
    __shared__ float red[128];

    float m = -1e30f;
    for (int c = threadIdx.x * 4; c < len; c += 512) {
        float4 v = *(const float4*)(p + c);
        m = fmaxf(m, fmaxf(fmaxf(v.x, v.y), fmaxf(v.z, v.w)));
    }
    red[threadIdx.x] = m;
    __syncthreads();
    for (int s = 64; s > 0; s >>= 1) {
        if (threadIdx.x < s) red[threadIdx.x] = fmaxf(red[threadIdx.x], red[threadIdx.x + s]);
        __syncthreads();
    }
    m = red[0];
    __syncthreads();

    float sum = 0.f;
    for (int c = threadIdx.x * 4; c < len; c += 512) {
        float4 v = *(const float4*)(p + c);
        sum += expf(v.x - m) + expf(v.y - m) + expf(v.z - m) + expf(v.w - m);
    }
    red[threadIdx.x] = sum;
    __syncthreads();
    for (int s = 64; s > 0; s >>= 1) {
        if (threadIdx.x < s) red[threadIdx.x] += red[threadIdx.x + s];
        __syncthreads();
    }
    float inv = 1.f / red[0];
    for (int c = threadIdx.x * 4; c < len; c += 512) {
        float4 v = *(const float4*)(p + c);
        float y[4] = {expf(v.x - m) * inv, expf(v.y - m) * inv,
                      expf(v.z - m) * inv, expf(v.w - m) * inv};
        __half h0 = __float2half_rn(y[0]), h1 = __float2half_rn(y[1]);
        __half h2 = __float2half_rn(y[2]), h3 = __float2half_rn(y[3]);
        *(__half2*)(ph + c) = __halves2half2(h0, h1);
        *(__half2*)(ph + c + 2) = __halves2half2(h2, h3);
        *(__half2*)(pl + c) = __halves2half2(
            __float2half_rn(y[0] - __half2float(h0)),
            __float2half_rn(y[1] - __half2float(h1)));
        *(__half2*)(pl + c + 2) = __halves2half2(
            __float2half_rn(y[2] - __half2float(h2)),
            __float2half_rn(y[3] - __half2float(h3)));
    }
    __half2 z = __halves2half2(__float2half_rn(0.f), __float2half_rn(0.f));
    for (int c = len + threadIdx.x * 4; c < len2; c += 512) {
        *(__half2*)(ph + c) = z;
        *(__half2*)(ph + c + 2) = z;
        *(__half2*)(pl + c) = z;
        *(__half2*)(pl + c + 2) = z;
    }
}

// ================= O = P @ V (fp16x2: P split, V single) -> split o =================
__global__ void __launch_bounds__(256, 2) attn_pv_mma_kernel() {
    extern __shared__ char sm[];
    const int ib = blockIdx.x, bh = blockIdx.y;
    const int b = bh >> 4, h = bh & 15;
    const int tid = threadIdx.x, lane = tid & 31, wid = tid >> 5;
    const int wm = wid & 3, wn = wid >> 2;
    const uint32_t smb = smem_u32(sm);

    const __half* Ph = g_ph + ((size_t)bh * LL + ib * 128) * LL;
    const __half* Pl = g_pl + ((size_t)bh * LL + ib * 128) * LL;
    const __half* Vh = g_vth + (size_t)bh * HD * LL;

    const int rowA_base = wm * 32 + (lane & 15);
    const int rowB_base = wn * 64 + (lane & 7) + ((lane >> 4) << 3);
    const uint32_t xorw = (uint32_t)((lane & 6) << 3);

    float acc[2][8][4];
#pragma unroll
    for (int i = 0; i < 2; i++)
#pragma unroll
        for (int j = 0; j < 8; j++)
#pragma unroll
            for (int q = 0; q < 4; q++) acc[i][j][q] = 0.f;

    auto issue = [&](int c, int stg) {
        const uint32_t sb = smb + (uint32_t)(stg * ATT_STG);
        const int j0 = c * 32;
#pragma unroll
        for (int i = 0; i < 6; i++) {
            int u = tid + (i << 8);
            int row = (u >> 2) & 127;
            int seg = u & 3;
            const __half* src = (u < 512) ? Ph : (u < 1024) ? Pl : Vh;
            uint32_t roff = (uint32_t)(u >> 9) * 8192;
            uint32_t dst = sb + roff + (uint32_t)(row * 64) +
                           (((uint32_t)(seg * 16)) ^ ((uint32_t)((row & 6) << 3)));
            CP_ASYNC16(dst, src + (size_t)row * LL + j0 + seg * 8);
        }
        CP_COMMIT();
    };

    const int NC = (ib + 1) * 4;
    issue(0, 0);
    issue(1, 1);
#pragma unroll 1
    for (int c = 0; c < NC; c++) {
        CP_WAIT1();
        __syncthreads();
        if (c + 2 < NC) issue(c + 2, (c + 2) % 3);
        else CP_COMMIT();
        const uint32_t stg = smb + (uint32_t)((c % 3) * ATT_STG);
#pragma unroll
        for (int kk = 0; kk < 2; kk++) {
            const uint32_t cbA = ((uint32_t)(kk * 32 + ((lane >> 4) << 4))) ^ xorw;
            const uint32_t cbB = ((uint32_t)(kk * 32 + (((lane >> 3) & 1) << 4))) ^ xorw;
            uint32_t ah[2][4], b4[4][4], fa[2][4];
#pragma unroll
            for (int mt = 0; mt < 2; mt++)
                LDSM4(ah[mt], stg + 0 + (uint32_t)((rowA_base + mt * 16) * 64) + cbA);
#pragma unroll
            for (int bt = 0; bt < 4; bt++)
                LDSM4(b4[bt], stg + 16384 + (uint32_t)((rowB_base + bt * 16) * 64) + cbB);
#pragma unroll
            for (int mt = 0; mt < 2; mt++)
                LDSM4(fa[mt], stg + 8192 + (uint32_t)((rowA_base + mt * 16) * 64) + cbA);
#pragma unroll
            for (int mt = 0; mt < 2; mt++)
#pragma unroll
                for (int nt = 0; nt < 8; nt++) {
                    const uint32_t* bb = b4[nt >> 1];
                    if (nt & 1) MMA_F16(acc[mt][nt], ah[mt], bb[2], bb[3]);
                    else        MMA_F16(acc[mt][nt], ah[mt], bb[0], bb[1]);
                }
#pragma unroll
            for (int mt = 0; mt < 2; mt++)
#pragma unroll
                for (int nt = 0; nt < 8; nt++) {
                    const uint32_t* bb = b4[nt >> 1];
                    if (nt & 1) MMA_F16(acc[mt][nt], fa[mt], bb[2], bb[3]);
                    else        MMA_F16(acc[mt][nt], fa[mt], bb[0], bb[1]);
                }
        }
    }

#pragma unroll
    for (int mt = 0; mt < 2; mt++) {
        const int qi = ib * 128 + wm * 32 + mt * 16 + (lane >> 2);
#pragma unroll
        for (int nt = 0; nt < 8; nt++) {
            const int d = wn * 64 + nt * 8 + ((lane & 3) << 1);
            size_t base0 = (size_t)(b * LL + qi) * DD + h * HD + d;
            size_t base1 = (size_t)(b * LL + qi + 8) * DD + h * HD + d;
            float v0 = acc[mt][nt][0], v1 = acc[mt][nt][1];
            float v2 = acc[mt][nt][2], v3 = acc[mt][nt][3];
            __half h0 = __float2half_rn(v0), h1 = __float2half_rn(v1);
            __half h2 = __float2half_rn(v2), h3 = __float2half_rn(v3);
            *(__half2*)(g_ah + base0) = __halves2half2(h0, h1);
            *(__half2*)(g_ah + base1) = __halves2half2(h2, h3);
            *(__half2*)(g_al + base0) = __halves2half2(
                __float2half_rn(v0 - __half2float(h0)),
                __float2half_rn(v1 - __half2float(h1)));
            *(__half2*)(g_al + base1) = __halves2half2(
                __float2half_rn(v2 - __half2float(h2)),
                __float2half_rn(v3 - __half2float(h3)));
        }
    }
}

// ================= launch =================
extern "C" void kernel_launch(void* const* d_in, const int* in_sizes, int n_in,
                              void* d_out, int out_size) {
    const float* x    = (const float*)d_in[0];
    const float* Wqkv = (const float*)d_in[1];
    const float* bqkv = (const float*)d_in[2];
    const float* Wo   = (const float*)d_in[3];
    const float* bo   = (const float*)d_in[4];
    const float* g1   = (const float*)d_in[5];
    const float* g2   = (const float*)d_in[6];
    const float* Wp   = (const float*)d_in[7];
    const float* bp   = (const float*)d_in[8];
    const float* Wff  = (const float*)d_in[9];
    const float* bff  = (const float*)d_in[10];
    float* out = (float*)d_out;

    __half *ah, *al, *fh, *fl, *wq, *wo, *wp, *wf;
    float *qkv, *x1;
    cudaGetSymbolAddress((void**)&ah,  g_ah);
    cudaGetSymbolAddress((void**)&al,  g_al);
    cudaGetSymbolAddress((void**)&fh,  g_fh);
    cudaGetSymbolAddress((void**)&fl,  g_fl);
    cudaGetSymbolAddress((void**)&wq,  g_WqkvT);
    cudaGetSymbolAddress((void**)&wo,  g_WoT);
    cudaGetSymbolAddress((void**)&wp,  g_WpT);
    cudaGetSymbolAddress((void**)&wf,  g_WffT);
    cudaGetSymbolAddress((void**)&qkv, g_qkv);
    cudaGetSymbolAddress((void**)&x1,  g_x1);

    cudaFuncSetAttribute(gemm_f16x2_kernel<false>,
                         cudaFuncAttributeMaxDynamicSharedMemorySize, GEMM_SMEM);
    cudaFuncSetAttribute(gemm_f16x2_kernel<true>,
                         cudaFuncAttributeMaxDynamicSharedMemorySize, GEMM_SMEM);
    cudaFuncSetAttribute(attn_scores_mma_kernel,
                         cudaFuncAttributeMaxDynamicSharedMemorySize, ATT_SMEM);
    cudaFuncSetAttribute(attn_pv_mma_kernel,
                         cudaFuncAttributeMaxDynamicSharedMemorySize, ATT_SMEM);

    dim3 tb(32, 8);

    // single stream, transposes scheduled just-in-time before consumers
    rope_table_kernel<<<LL, 64>>>();
    transpose_half_kernel<<<dim3(D3 / 32, DD / 32), tb>>>(Wqkv, wq, DD, D3);
    rmsnorm_split_kernel<<<MROWS, 256>>>(x, g1, ah, al);

    // qkv = h @ Wqkv + bqkv   (launch #4 — profiled)
    gemm_f16x2_kernel<false><<<dim3(MROWS / TM, D3 / TN), 256, GEMM_SMEM>>>(
        ah, al, wq, bqkv, nullptr, qkv, nullptr, nullptr, MROWS, D3, DD);

    {
        int total = BB * LL * HH * 64;
        rope_apply_split_kernel<<<(total + 255) / 256, 256>>>();
    }
    v_transpose_kernel<<<dim3(LL / 32, HD / 32, BB * HH), tb>>>();
    attn_scores_mma_kernel<<<dim3(LL / 128, LL / 128, BB * HH), 256, ATT_SMEM>>>();
    softmax_kernel<<<BB * HH * LL, 128>>>();
    attn_pv_mma_kernel<<<dim3(LL / 128, BB * HH), 256, ATT_SMEM>>>();

    transpose_half_kernel<<<dim3(DD / 32, DD / 32), tb>>>(Wo, wo, DD, DD);
    gemm_f16x2_kernel<false><<<dim3(MROWS / TM, DD / TN), 256, GEMM_SMEM>>>(
        ah, al, wo, bo, x, x1, nullptr, nullptr, MROWS, DD, DD);

    rmsnorm_split_kernel<<<MROWS, 256>>>(x1, g2, ah, al);

    transpose_half_interleave_kernel<<<dim3(D8 / 32, DD / 32), tb>>>(Wp, wp, DD, D8);
    gemm_f16x2_kernel<true><<<dim3(MROWS / TM, D8 / TN), 256, GEMM_SMEM>>>(
        ah, al, wp, bp, nullptr, nullptr, fh, fl, MROWS, D8, DD);

    transpose_half_kernel<<<dim3(DD / 32, D4 / 32), tb>>>(Wff, wf, D4, DD);
    gemm_f16x2_kernel<false><<<dim3(MROWS / TM, DD / TN), 256, GEMM_SMEM>>>(
        fh, fl, wf, bff, x1, out, nullptr, nullptr, MROWS, DD, D4);
}

// round 11
// speedup vs baseline: 2.3581x; 1.6243x over previous
#include <cuda_runtime.h>
#include <cuda_fp16.h>
#include <math.h>
#include <stdint.h>

// Problem constants
#define BB 2
#define LL 2048
#define DD 2048
#define HH 16
#define HD 128
#define MROWS (BB * LL)        // 4096
#define D3 (3 * DD)            // 6144
#define D8 (8 * DD)            // 16384
#define D4 (4 * DD)            // 8192

// ---------------- scratch ----------------
__device__ float g_qkv[(size_t)MROWS * D3];
__device__ float g_s  [(size_t)BB * HH * LL * LL];
__device__ float g_x1 [(size_t)MROWS * DD];
__device__ float g_cos[LL * 64];
__device__ float g_sin[LL * 64];

// single-fp16 activations
__device__ __align__(16) __half g_ah[(size_t)MROWS * DD];
__device__ __align__(16) __half g_fh[(size_t)MROWS * D4];

__device__ __align__(16) __half g_qh[(size_t)BB * HH * LL * HD];
__device__ __align__(16) __half g_kh[(size_t)BB * HH * LL * HD];
__device__ __align__(16) __half g_vth[(size_t)BB * HH * HD * LL];
__device__ __align__(16) __half g_ph[(size_t)BB * HH * LL * LL];

// single-fp16 transposed weights [N,K]
__device__ __align__(16) __half g_WqkvT[(size_t)D3 * DD];
__device__ __align__(16) __half g_WoT[(size_t)DD * DD];
__device__ __align__(16) __half g_WpT[(size_t)D8 * DD];
__device__ __align__(16) __half g_WffT[(size_t)DD * D4];

// ================= helpers =================
__device__ __forceinline__ uint32_t smem_u32(const void* p) {
    uint32_t a;
    asm("{ .reg .u64 t; cvta.to.shared.u64 t, %1; cvt.u32.u64 %0, t; }" : "=r"(a) : "l"(p));
    return a;
}

#define CP_ASYNC16(dst, src) \
    asm volatile("cp.async.cg.shared.global [%0], [%1], 16;" :: "r"(dst), "l"(src) : "memory")
#define CP_COMMIT() asm volatile("cp.async.commit_group;" ::: "memory")
#define CP_WAIT1()  asm volatile("cp.async.wait_group 1;" ::: "memory")

#define LDSM4(r, addr) \
    asm volatile("ldmatrix.sync.aligned.m8n8.x4.shared.b16 {%0,%1,%2,%3}, [%4];" \
        : "=r"((r)[0]), "=r"((r)[1]), "=r"((r)[2]), "=r"((r)[3]) : "r"(addr))

#define MMA_F16(d, a, b0, b1) \
    asm volatile("mma.sync.aligned.m16n8k16.row.col.f32.f16.f16.f32 " \
        "{%0,%1,%2,%3}, {%4,%5,%6,%7}, {%8,%9}, {%0,%1,%2,%3};" \
        : "+f"((d)[0]), "+f"((d)[1]), "+f"((d)[2]), "+f"((d)[3]) \
        : "r"((a)[0]), "r"((a)[1]), "r"((a)[2]), "r"((a)[3]), "r"(b0), "r"(b1))

// ================= RoPE tables =================
__global__ void rope_table_kernel() {
    int p = blockIdx.x, i = threadIdx.x;
    double inv_freq = pow(10000.0, -(double)(2 * i) / (double)HD);
    double ang = (double)p * inv_freq;
    g_cos[p * 64 + i] = (float)cos(ang);
    g_sin[p * 64 + i] = (float)sin(ang);
}

// ================= RMSNorm -> fp16 =================
__global__ void rmsnorm_half_kernel(const float* __restrict__ x,
                                    const float* __restrict__ g,
                                    __half* __restrict__ o) {
    int row = blockIdx.x;
    const float* xr = x + (size_t)row * DD;
    float ss = 0.f;
    for (int c = threadIdx.x * 4; c < DD; c += blockDim.x * 4) {
        float4 v = *(const float4*)(xr + c);
        ss += v.x * v.x + v.y * v.y + v.z * v.z + v.w * v.w;
    }
    __shared__ float red[256];
    red[threadIdx.x] = ss;
    __syncthreads();
    for (int s = blockDim.x / 2; s > 0; s >>= 1) {
        if (threadIdx.x < s) red[threadIdx.x] += red[threadIdx.x + s];
        __syncthreads();
    }
    float scale = rsqrtf(red[0] / (float)DD + 1e-8f);
    for (int c = threadIdx.x * 4; c < DD; c += blockDim.x * 4) {
        float4 v = *(const float4*)(xr + c);
        float4 gv = *(const float4*)(g + c);
        __half2 h0 = __halves2half2(__float2half_rn(v.x * scale * gv.x),
                                    __float2half_rn(v.y * scale * gv.y));
        __half2 h1 = __halves2half2(__float2half_rn(v.z * scale * gv.z),
                                    __float2half_rn(v.w * scale * gv.w));
        *(__half2*)(o + (size_t)row * DD + c) = h0;
        *(__half2*)(o + (size_t)row * DD + c + 2) = h1;
    }
}

// ================= weight transpose -> fp16 =================
__global__ void transpose_half_kernel(const float* __restrict__ W,
                                      __half* __restrict__ T,
                                      int K, int N) {
    __shared__ float t[32][33];
    int n0 = blockIdx.x * 32, k0 = blockIdx.y * 32;
    int tx = threadIdx.x, ty = threadIdx.y;
#pragma unroll
    for (int r = 0; r < 4; r++) {
        int k = ty + r * 8;
        t[k][tx] = W[(size_t)(k0 + k) * N + n0 + tx];
    }
    __syncthreads();
#pragma unroll
    for (int r = 0; r < 4; r++) {
        int n = ty + r * 8;
        T[(size_t)(n0 + n) * K + k0 + tx] = __float2half_rn(t[tx][n]);
    }
}

// Wp transpose with gate/value interleave
__global__ void transpose_half_interleave_kernel(const float* __restrict__ W,
                                                 __half* __restrict__ T,
                                                 int K, int N) {
    __shared__ float t[32][33];
    int n0 = blockIdx.x * 32, k0 = blockIdx.y * 32;
    int tx = threadIdx.x, ty = threadIdx.y;
#pragma unroll
    for (int r = 0; r < 4; r++) {
        int k = ty + r * 8;
        t[k][tx] = W[(size_t)(k0 + k) * N + n0 + tx];
    }
    __syncthreads();
#pragma unroll
    for (int r = 0; r < 4; r++) {
        int n = ty + r * 8;
        int ncol = n0 + n;
        int rout = ((ncol & (D4 - 1)) << 1) | (ncol >> 13);
        T[(size_t)rout * K + k0 + tx] = __float2half_rn(t[tx][n]);
    }
}

// ====== fp16 GEMM: C = A[M,K] @ B[N,K]^T; 128x128, 256 thr, 3-stage, 2 CTAs/SM ======
#define TM 128
#define TN 128
#define KC 32
#define A_OFF 0
#define B_OFF 8192
#define STG_BYTES 16384
#define GEMM_SMEM (3 * STG_BYTES)

template <bool SWIGLU>
__global__ void __launch_bounds__(256, 2) gemm_f16_kernel(
    const __half* __restrict__ A, const __half* __restrict__ B,
    const float* __restrict__ bias, const float* __restrict__ R,
    float* __restrict__ C, __half* __restrict__ Oh,
    int M, int N, int K)
{
    extern __shared__ char sm[];
    const int tid = threadIdx.x;
    const int lane = tid & 31;
    const int wid = tid >> 5;
    const int wm = wid & 3;
    const int wn = wid >> 2;
    const int bm = blockIdx.x * TM;
    const int bn = blockIdx.y * TN;
    const uint32_t smb = smem_u32(sm);

    const int rowA_base = wm * 32 + (lane & 15);
    const int rowB_base = wn * 64 + (lane & 7) + ((lane >> 4) << 3);
    const uint32_t xorw = (uint32_t)((lane & 6) << 3);

    float acc[2][8][4];
#pragma unroll
    for (int i = 0; i < 2; i++)
#pragma unroll
        for (int j = 0; j < 8; j++)
#pragma unroll
            for (int q = 0; q < 4; q++) acc[i][j][q] = 0.f;

    // 1024 x 16B per chunk, 4 per thread
    auto issue_chunk = [&](int k0, int stg) {
        const uint32_t sbase = smb + stg * STG_BYTES;
#pragma unroll
        for (int i = 0; i < 4; i++) {
            int u = tid + (i << 8);
            const __half* src;
            uint32_t roff;
            int row;
            if (u < 512) { row = u >> 2;         src = A + (size_t)(bm + row) * K; roff = A_OFF; }
            else         { row = (u - 512) >> 2; src = B + (size_t)(bn + row) * K; roff = B_OFF; }
            int seg = u & 3;
            uint32_t dst = sbase + roff + (uint32_t)(row * 64) +
                           (((uint32_t)(seg * 16)) ^ ((uint32_t)((row & 6) << 3)));
            CP_ASYNC16(dst, src + k0 + seg * 8);
        }
        CP_COMMIT();
    };

    const int NC = K / KC;
    issue_chunk(0, 0);
    issue_chunk(KC, 1);

    for (int c = 0; c < NC; ++c) {
        CP_WAIT1();
        __syncthreads();
        if (c + 2 < NC) issue_chunk((c + 2) * KC, (c + 2) % 3);
        else CP_COMMIT();

        const uint32_t stg = smb + (uint32_t)((c % 3) * STG_BYTES);

#pragma unroll
        for (int kk = 0; kk < 2; kk++) {
            const uint32_t cbA = ((uint32_t)(kk * 32 + ((lane >> 4) << 4))) ^ xorw;
            const uint32_t cbB = ((uint32_t)(kk * 32 + (((lane >> 3) & 1) << 4))) ^ xorw;

            uint32_t ah[2][4], b4[4][4];
#pragma unroll
            for (int mt = 0; mt < 2; mt++)
                LDSM4(ah[mt], stg + A_OFF + (uint32_t)((rowA_base + mt * 16) * 64) + cbA);
#pragma unroll
            for (int bt = 0; bt < 4; bt++)
                LDSM4(b4[bt], stg + B_OFF + (uint32_t)((rowB_base + bt * 16) * 64) + cbB);
#pragma unroll
            for (int mt = 0; mt < 2; mt++)
#pragma unroll
                for (int nt = 0; nt < 8; nt++) {
                    const uint32_t* b = b4[nt >> 1];
                    if (nt & 1) MMA_F16(acc[mt][nt], ah[mt], b[2], b[3]);
                    else        MMA_F16(acc[mt][nt], ah[mt], b[0], b[1]);
                }
        }
    }

    // ---- epilogue ----
    if (SWIGLU) {
        const int outN = N >> 1;
#pragma unroll
        for (int mt = 0; mt < 2; mt++) {
            const int m = bm + wm * 32 + mt * 16 + (lane >> 2);
#pragma unroll
            for (int nt = 0; nt < 8; nt++) {
                const int nperm = bn + wn * 64 + nt * 8 + ((lane & 3) << 1);
                const int i = nperm >> 1;
                float bg = bias[i];
                float bv = bias[outN + i];
                float g0 = acc[mt][nt][0] + bg, v0 = acc[mt][nt][1] + bv;
                float g1 = acc[mt][nt][2] + bg, v1 = acc[mt][nt][3] + bv;
                float r0 = g0 / (1.f + expf(-g0)) * v0;
                float r1 = g1 / (1.f + expf(-g1)) * v1;
                Oh[(size_t)m * outN + i] = __float2half_rn(r0);
                Oh[(size_t)(m + 8) * outN + i] = __float2half_rn(r1);
            }
        }
    } else {
#pragma unroll
        for (int mt = 0; mt < 2; mt++) {
            const int m = bm + wm * 32 + mt * 16 + (lane >> 2);
#pragma unroll
            for (int nt = 0; nt < 8; nt++) {
                const int n = bn + wn * 64 + nt * 8 + ((lane & 3) << 1);
                float2 b2 = *(const float2*)(bias + n);
                float2 o0, o1;
                o0.x = acc[mt][nt][0] + b2.x;
                o0.y = acc[mt][nt][1] + b2.y;
                o1.x = acc[mt][nt][2] + b2.x;
                o1.y = acc[mt][nt][3] + b2.y;
                if (R) {
                    float2 r0 = *(const float2*)(R + (size_t)m * N + n);
                    float2 r1 = *(const float2*)(R + (size_t)(m + 8) * N + n);
                    o0.x += r0.x; o0.y += r0.y;
                    o1.x += r1.x; o1.y += r1.y;
                }
                *(float2*)(C + (size_t)m * N + n) = o0;
                *(float2*)(C + (size_t)(m + 8) * N + n) = o1;
            }
        }
    }
}

// ================= RoPE: qkv fp32 -> fp16 q,k in [B,H,L,HD] =================
__global__ void rope_apply_half_kernel() {
    int idx = blockIdx.x * blockDim.x + threadIdx.x;
    if (idx >= BB * LL * HH * 64) return;
    int d = idx & 63;
    int h = (idx >> 6) & (HH - 1);
    int bl = idx >> 10;
    int b = bl >> 11;
    int l = bl & (LL - 1);
    float c = g_cos[l * 64 + d];
    float s = g_sin[l * 64 + d];
    size_t src = (size_t)bl * D3 + h * HD + d;
    size_t dst = ((size_t)(b * HH + h) * LL + l) * HD + d;

    float q1 = g_qkv[src], q2 = g_qkv[src + 64];
    g_qh[dst]      = __float2half_rn(q1 * c - q2 * s);
    g_qh[dst + 64] = __float2half_rn(q2 * c + q1 * s);

    size_t ks = src + DD;
    float k1 = g_qkv[ks], k2 = g_qkv[ks + 64];
    g_kh[dst]      = __float2half_rn(k1 * c - k2 * s);
    g_kh[dst + 64] = __float2half_rn(k2 * c + k1 * s);
}

// ================= V transpose -> fp16 [B,H,HD,L] =================
__global__ void v_transpose_kernel() {
    __shared__ float t[32][33];
    int l0 = blockIdx.x * 32, d0 = blockIdx.y * 32, bh = blockIdx.z;
    int b = bh >> 4, h = bh & 15;
    int tx = threadIdx.x, ty = threadIdx.y;
#pragma unroll
    for (int r = 0; r < 4; r++) {
        int l = ty + r * 8;
        t[l][tx] = g_qkv[(size_t)(b * LL + l0 + l) * D3 + 2 * DD + h * HD + d0 + tx];
    }
    __syncthreads();
#pragma unroll
    for (int r = 0; r < 4; r++) {
        int d = ty + r * 8;
        g_vth[((size_t)bh * HD + d0 + d) * LL + l0 + tx] = __float2half_rn(t[tx][d]);
    }
}

// ================= attention scores (fp16 single) =================
#define ATT_STG 16384
#define ATT_SMEM (3 * ATT_STG)

__global__ void __launch_bounds__(256, 2) attn_scores_mma_kernel() {
    extern __shared__ char sm[];
    const int jb = blockIdx.x, ib = blockIdx.y, bh = blockIdx.z;
    if (jb > ib) return;
    const int tid = threadIdx.x, lane = tid & 31, wid = tid >> 5;
    const int wm = wid & 3, wn = wid >> 2;
    const uint32_t smb = smem_u32(sm);

    const __half* Qh = g_qh + ((size_t)bh * LL + ib * 128) * HD;
    const __half* Kh = g_kh + ((size_t)bh * LL + jb * 128) * HD;

    const int rowA_base = wm * 32 + (lane & 15);
    const int rowB_base = wn * 64 + (lane & 7) + ((lane >> 4) << 3);
    const uint32_t xorw = (uint32_t)((lane & 6) << 3);

    float acc[2][8][4];
#pragma unroll
    for (int i = 0; i < 2; i++)
#pragma unroll
        for (int j = 0; j < 8; j++)
#pragma unroll
            for (int q = 0; q < 4; q++) acc[i][j][q] = 0.f;

    auto issue = [&](int c, int stg) {
        const uint32_t sb = smb + (uint32_t)(stg * ATT_STG);
        const int k0 = c * 32;
#pragma unroll
        for (int i = 0; i < 4; i++) {
            int u = tid + (i << 8);
            int row = (u >> 2) & 127;
            int seg = u & 3;
            const __half* src = (u < 512) ? Qh : Kh;
            uint32_t roff = (u < 512) ? 0u : 8192u;
            uint32_t dst = sb + roff + (uint32_t)(row * 64) +
                           (((uint32_t)(seg * 16)) ^ ((uint32_t)((row & 6) << 3)));
            CP_ASYNC16(dst, src + (size_t)row * HD + k0 + seg * 8);
        }
        CP_COMMIT();
    };

    issue(0, 0);
    issue(1, 1);
#pragma unroll 1
    for (int c = 0; c < 4; c++) {
        CP_WAIT1();
        __syncthreads();
        if (c + 2 < 4) issue(c + 2, (c + 2) % 3);
        else CP_COMMIT();
        const uint32_t stg = smb + (uint32_t)((c % 3) * ATT_STG);
#pragma unroll
        for (int kk = 0; kk < 2; kk++) {
            const uint32_t cbA = ((uint32_t)(kk * 32 + ((lane >> 4) << 4))) ^ xorw;
            const uint32_t cbB = ((uint32_t)(kk * 32 + (((lane >> 3) & 1) << 4))) ^ xorw;
            uint32_t ah[2][4], b4[4][4];
#pragma unroll
            for (int mt = 0; mt < 2; mt++)
                LDSM4(ah[mt], stg + 0 + (uint32_t)((rowA_base + mt * 16) * 64) + cbA);
#pragma unroll
            for (int bt = 0; bt < 4; bt++)
                LDSM4(b4[bt], stg + 8192 + (uint32_t)((rowB_base + bt * 16) * 64) + cbB);
#pragma unroll
            for (int mt = 0; mt < 2; mt++)
#pragma unroll
                for (int nt = 0; nt < 8; nt++) {
                    const uint32_t* b = b4[nt >> 1];
                    if (nt & 1) MMA_F16(acc[mt][nt], ah[mt], b[2], b[3]);
                    else        MMA_F16(acc[mt][nt], ah[mt], b[0], b[1]);
                }
        }
    }

    const float scale = 0.08838834764831845f;
#pragma unroll
    for (int mt = 0; mt < 2; mt++) {
        const int i0 = ib * 128 + wm * 32 + mt * 16 + (lane >> 2);
#pragma unroll
        for (int nt = 0; nt < 8; nt++) {
            const int j0 = jb * 128 + wn * 64 + nt * 8 + ((lane & 3) << 1);
            float2 o0, o1;
            o0.x = (j0     <= i0)     ? acc[mt][nt][0] * scale : -1e30f;
            o0.y = (j0 + 1 <= i0)     ? acc[mt][nt][1] * scale : -1e30f;
            o1.x = (j0     <= i0 + 8) ? acc[mt][nt][2] * scale : -1e30f;
            o1.y = (j0 + 1 <= i0 + 8) ? acc[mt][nt][3] * scale : -1e30f;
            *(float2*)(g_s + ((size_t)bh * LL + i0) * LL + j0) = o0;
            *(float2*)(g_s + ((size_t)bh * LL + i0 + 8) * LL + j0) = o1;
        }
    }
}

// ========== row softmax -> fp16 P ==========
__global__ void softmax_kernel() {
    int r = blockIdx.x;
    int i = r & (LL - 1);
    int len = ((i >> 6) + 1) << 6;
    int len2 = ((i >> 7) + 1) << 7;
    const float* p = g_s + (size_t)r * LL;
    __half* ph = g_ph + (size_t)r * LL;
    __shared__ float red[128];

    float m = -1e30f;
    for (int c = threadIdx.x * 4; c < len; c += 512) {
        float4 v = *(const float4*)(p + c);
        m = fmaxf(m, fmaxf(fmaxf(v.x, v.y), fmaxf(v.z, v.w)));
    }
    red[threadIdx.x] = m;
    __syncthreads();
    for (int s = 64; s > 0; s >>= 1) {
        if (threadIdx.x < s) red[threadIdx.x] = fmaxf(red[threadIdx.x], red[threadIdx.x + s]);
        __syncthreads();
    }
    m = red[0];
    __syncthreads();

    float sum = 0.f;
    for (int c = threadIdx.x * 4; c < len; c += 512) {
        float4 v = *(const float4*)(p + c);
        sum += expf(v.x - m) + expf(v.y - m) + expf(v.z - m) + expf(v.w - m);
    }
    red[threadIdx.x] = sum;
    __syncthreads();
    for (int s = 64; s > 0; s >>= 1) {
        if (threadIdx.x < s) red[threadIdx.x] += red[threadIdx.x + s];
        __syncthreads();
    }
    float inv = 1.f / red[0];
    for (int c = threadIdx.x * 4; c < len; c += 512) {
        float4 v = *(const float4*)(p + c);
        *(__half2*)(ph + c) = __halves2half2(
            __float2half_rn(expf(v.x - m) * inv), __float2half_rn(expf(v.y - m) * inv));
        *(__half2*)(ph + c + 2) = __halves2half2(
            __float2half_rn(expf(v.z - m) * inv), __float2half_rn(expf(v.w - m) * inv));
    }
    __half2 z = __halves2half2(__float2half_rn(0.f), __float2half_rn(0.f));
    for (int c = len + threadIdx.x * 4; c < len2; c += 512) {
        *(__half2*)(ph + c) = z;
        *(__half2*)(ph + c + 2) = z;
    }
}

// ================= O = P @ V (fp16 single) -> fp16 o =================
__global__ void __launch_bounds__(256, 2) attn_pv_mma_kernel() {
    extern __shared__ char sm[];
    const int ib = blockIdx.x, bh = blockIdx.y;
    const int b = bh >> 4, h = bh & 15;
    const int tid = threadIdx.x, lane = tid & 31, wid = tid >> 5;
    const int wm = wid & 3, wn = wid >> 2;
    const uint32_t smb = smem_u32(sm);

    const __half* Ph = g_ph + ((size_t)bh * LL + ib * 128) * LL;
    const __half* Vh = g_vth + (size_t)bh * HD * LL;

    const int rowA_base = wm * 32 + (lane & 15);
    const int rowB_base = wn * 64 + (lane & 7) + ((lane >> 4) << 3);
    const uint32_t xorw = (uint32_t)((lane & 6) << 3);

    float acc[2][8][4];
#pragma unroll
    for (int i = 0; i < 2; i++)
#pragma unroll
        for (int j = 0; j < 8; j++)
#pragma unroll
            for (int q = 0; q < 4; q++) acc[i][j][q] = 0.f;

    auto issue = [&](int c, int stg) {
        const uint32_t sb = smb + (uint32_t)(stg * ATT_STG);
        const int j0 = c * 32;
#pragma unroll
        for (int i = 0; i < 4; i++) {
            int u = tid + (i << 8);
            int row = (u >> 2) & 127;
            int seg = u & 3;
            const __half* src = (u < 512) ? Ph : Vh;
            uint32_t roff = (u < 512) ? 0u : 8192u;
            uint32_t dst = sb + roff + (uint32_t)(row * 64) +
                           (((uint32_t)(seg * 16)) ^ ((uint32_t)((row & 6) << 3)));
            CP_ASYNC16(dst, src + (size_t)row * LL + j0 + seg * 8);
        }
        CP_COMMIT();
    };

    const int NC = (ib + 1) * 4;
    issue(0, 0);
    issue(1, 1);
#pragma unroll 1
    for (int c = 0; c < NC; c++) {
        CP_WAIT1();
        __syncthreads();
        if (c + 2 < NC) issue(c + 2, (c + 2) % 3);
        else CP_COMMIT();
        const uint32_t stg = smb + (uint32_t)((c % 3) * ATT_STG);
#pragma unroll
        for (int kk = 0; kk < 2; kk++) {
            const uint32_t cbA = ((uint32_t)(kk * 32 + ((lane >> 4) << 4))) ^ xorw;
            const uint32_t cbB = ((uint32_t)(kk * 32 + (((lane >> 3) & 1) << 4))) ^ xorw;
            uint32_t ah[2][4], b4[4][4];
#pragma unroll
            for (int mt = 0; mt < 2; mt++)
                LDSM4(ah[mt], stg + 0 + (uint32_t)((rowA_base + mt * 16) * 64) + cbA);
#pragma unroll
            for (int bt = 0; bt < 4; bt++)
                LDSM4(b4[bt], stg + 8192 + (uint32_t)((rowB_base + bt * 16) * 64) + cbB);
#pragma unroll
            for (int mt = 0; mt < 2; mt++)
#pragma unroll
                for (int nt = 0; nt < 8; nt++) {
                    const uint32_t* bb = b4[nt >> 1];
                    if (nt & 1) MMA_F16(acc[mt][nt], ah[mt], bb[2], bb[3]);
                    else        MMA_F16(acc[mt][nt], ah[mt], bb[0], bb[1]);
                }
        }
    }

#pragma unroll
    for (int mt = 0; mt < 2; mt++) {
        const int qi = ib * 128 + wm * 32 + mt * 16 + (lane >> 2);
#pragma unroll
        for (int nt = 0; nt < 8; nt++) {
            const int d = wn * 64 + nt * 8 + ((lane & 3) << 1);
            size_t base0 = (size_t)(b * LL + qi) * DD + h * HD + d;
            size_t base1 = (size_t)(b * LL + qi + 8) * DD + h * HD + d;
            *(__half2*)(g_ah + base0) = __halves2half2(
                __float2half_rn(acc[mt][nt][0]), __float2half_rn(acc[mt][nt][1]));
            *(__half2*)(g_ah + base1) = __halves2half2(
                __float2half_rn(acc[mt][nt][2]), __float2half_rn(acc[mt][nt][3]));
        }
    }
}

// ================= launch =================
extern "C" void kernel_launch(void* const* d_in, const int* in_sizes, int n_in,
                              void* d_out, int out_size) {
    const float* x    = (const float*)d_in[0];
    const float* Wqkv = (const float*)d_in[1];
    const float* bqkv = (const float*)d_in[2];
    const float* Wo   = (const float*)d_in[3];
    const float* bo   = (const float*)d_in[4];
    const float* g1   = (const float*)d_in[5];
    const float* g2   = (const float*)d_in[6];
    const float* Wp   = (const float*)d_in[7];
    const float* bp   = (const float*)d_in[8];
    const float* Wff  = (const float*)d_in[9];
    const float* bff  = (const float*)d_in[10];
    float* out = (float*)d_out;

    __half *ah, *fh, *wq, *wo, *wp, *wf;
    float *qkv, *x1;
    cudaGetSymbolAddress((void**)&ah,  g_ah);
    cudaGetSymbolAddress((void**)&fh,  g_fh);
    cudaGetSymbolAddress((void**)&wq,  g_WqkvT);
    cudaGetSymbolAddress((void**)&wo,  g_WoT);
    cudaGetSymbolAddress((void**)&wp,  g_WpT);
    cudaGetSymbolAddress((void**)&wf,  g_WffT);
    cudaGetSymbolAddress((void**)&qkv, g_qkv);
    cudaGetSymbolAddress((void**)&x1,  g_x1);

    cudaFuncSetAttribute(gemm_f16_kernel<false>,
                         cudaFuncAttributeMaxDynamicSharedMemorySize, GEMM_SMEM);
    cudaFuncSetAttribute(gemm_f16_kernel<true>,
                         cudaFuncAttributeMaxDynamicSharedMemorySize, GEMM_SMEM);
    cudaFuncSetAttribute(attn_scores_mma_kernel,
                         cudaFuncAttributeMaxDynamicSharedMemorySize, ATT_SMEM);
    cudaFuncSetAttribute(attn_pv_mma_kernel,
                         cudaFuncAttributeMaxDynamicSharedMemorySize, ATT_SMEM);

    dim3 tb(32, 8);

    rope_table_kernel<<<LL, 64>>>();
    transpose_half_kernel<<<dim3(D3 / 32, DD / 32), tb>>>(Wqkv, wq, DD, D3);
    rmsnorm_half_kernel<<<MROWS, 256>>>(x, g1, ah);

    // qkv = h @ Wqkv + bqkv   (launch #4 — profiled)
    gemm_f16_kernel<false><<<dim3(MROWS / TM, D3 / TN), 256, GEMM_SMEM>>>(
        ah, wq, bqkv, nullptr, qkv, nullptr, MROWS, D3, DD);

    {
        int total = BB * LL * HH * 64;
        rope_apply_half_kernel<<<(total + 255) / 256, 256>>>();
    }
    v_transpose_kernel<<<dim3(LL / 32, HD / 32, BB * HH), tb>>>();
    attn_scores_mma_kernel<<<dim3(LL / 128, LL / 128, BB * HH), 256, ATT_SMEM>>>();
    softmax_kernel<<<BB * HH * LL, 128>>>();
    attn_pv_mma_kernel<<<dim3(LL / 128, BB * HH), 256, ATT_SMEM>>>();

    transpose_half_kernel<<<dim3(DD / 32, DD / 32), tb>>>(Wo, wo, DD, DD);
    gemm_f16_kernel<false><<<dim3(MROWS / TM, DD / TN), 256, GEMM_SMEM>>>(
        ah, wo, bo, x, x1, nullptr, MROWS, DD, DD);

    rmsnorm_half_kernel<<<MROWS, 256>>>(x1, g2, ah);

    transpose_half_interleave_kernel<<<dim3(D8 / 32, DD / 32), tb>>>(Wp, wp, DD, D8);
    gemm_f16_kernel<true><<<dim3(MROWS / TM, D8 / TN), 256, GEMM_SMEM>>>(
        ah, wp, bp, nullptr, nullptr, fh, MROWS, D8, DD);

    transpose_half_kernel<<<dim3(DD / 32, D4 / 32), tb>>>(Wff, wf, D4, DD);
    gemm_f16_kernel<false><<<dim3(MROWS / TM, DD / TN), 256, GEMM_SMEM>>>(
        fh, wf, bff, x1, out, nullptr, MROWS, DD, D4);
}

// round 13
// speedup vs baseline: 2.3976x; 1.0167x over previous
#include <cuda_runtime.h>
#include <cuda_fp16.h>
#include <math.h>
#include <stdint.h>

// Problem constants
#define BB 2
#define LL 2048
#define DD 2048
#define HH 16
#define HD 128
#define MROWS (BB * LL)        // 4096
#define D3 (3 * DD)            // 6144
#define D8 (8 * DD)            // 16384
#define D4 (4 * DD)            // 8192

// ---------------- scratch ----------------
__device__ float g_x1 [(size_t)MROWS * DD];
__device__ float g_cos[LL * 64];
__device__ float g_sin[LL * 64];

__device__ __align__(16) __half g_qkvh[(size_t)MROWS * D3];      // fp16 qkv
__device__ __align__(16) __half g_sh[(size_t)BB * HH * LL * LL]; // fp16 scores

__device__ __align__(16) __half g_ah[(size_t)MROWS * DD];
__device__ __align__(16) __half g_fh[(size_t)MROWS * D4];

__device__ __align__(16) __half g_qh[(size_t)BB * HH * LL * HD];
__device__ __align__(16) __half g_kh[(size_t)BB * HH * LL * HD];
__device__ __align__(16) __half g_vth[(size_t)BB * HH * HD * LL];
__device__ __align__(16) __half g_ph[(size_t)BB * HH * LL * LL];

__device__ __align__(16) __half g_WqkvT[(size_t)D3 * DD];
__device__ __align__(16) __half g_WoT[(size_t)DD * DD];
__device__ __align__(16) __half g_WpT[(size_t)D8 * DD];
__device__ __align__(16) __half g_WffT[(size_t)DD * D4];

// ================= helpers =================
__device__ __forceinline__ uint32_t smem_u32(const void* p) {
    uint32_t a;
    asm("{ .reg .u64 t; cvta.to.shared.u64 t, %1; cvt.u32.u64 %0, t; }" : "=r"(a) : "l"(p));
    return a;
}

#define CP_ASYNC16(dst, src) \
    asm volatile("cp.async.cg.shared.global [%0], [%1], 16;" :: "r"(dst), "l"(src) : "memory")
#define CP_COMMIT() asm volatile("cp.async.commit_group;" ::: "memory")
#define CP_WAIT1()  asm volatile("cp.async.wait_group 1;" ::: "memory")

#define LDSM4(r, addr) \
    asm volatile("ldmatrix.sync.aligned.m8n8.x4.shared.b16 {%0,%1,%2,%3}, [%4];" \
        : "=r"((r)[0]), "=r"((r)[1]), "=r"((r)[2]), "=r"((r)[3]) : "r"(addr))

#define MMA_F16(d, a, b0, b1) \
    asm volatile("mma.sync.aligned.m16n8k16.row.col.f32.f16.f16.f32 " \
        "{%0,%1,%2,%3}, {%4,%5,%6,%7}, {%8,%9}, {%0,%1,%2,%3};" \
        : "+f"((d)[0]), "+f"((d)[1]), "+f"((d)[2]), "+f"((d)[3]) \
        : "r"((a)[0]), "r"((a)[1]), "r"((a)[2]), "r"((a)[3]), "r"(b0), "r"(b1))

// ================= RoPE tables =================
__global__ void rope_table_kernel() {
    int p = blockIdx.x, i = threadIdx.x;
    double inv_freq = pow(10000.0, -(double)(2 * i) / (double)HD);
    double ang = (double)p * inv_freq;
    g_cos[p * 64 + i] = (float)cos(ang);
    g_sin[p * 64 + i] = (float)sin(ang);
}

// ================= RMSNorm -> fp16 =================
__global__ void rmsnorm_half_kernel(const float* __restrict__ x,
                                    const float* __restrict__ g,
                                    __half* __restrict__ o) {
    int row = blockIdx.x;
    const float* xr = x + (size_t)row * DD;
    float ss = 0.f;
    for (int c = threadIdx.x * 4; c < DD; c += blockDim.x * 4) {
        float4 v = *(const float4*)(xr + c);
        ss += v.x * v.x + v.y * v.y + v.z * v.z + v.w * v.w;
    }
    __shared__ float red[256];
    red[threadIdx.x] = ss;
    __syncthreads();
    for (int s = blockDim.x / 2; s > 0; s >>= 1) {
        if (threadIdx.x < s) red[threadIdx.x] += red[threadIdx.x + s];
        __syncthreads();
    }
    float scale = rsqrtf(red[0] / (float)DD + 1e-8f);
    for (int c = threadIdx.x * 4; c < DD; c += blockDim.x * 4) {
        float4 v = *(const float4*)(xr + c);
        float4 gv = *(const float4*)(g + c);
        *(__half2*)(o + (size_t)row * DD + c) = __halves2half2(
            __float2half_rn(v.x * scale * gv.x), __float2half_rn(v.y * scale * gv.y));
        *(__half2*)(o + (size_t)row * DD + c + 2) = __halves2half2(
            __float2half_rn(v.z * scale * gv.z), __float2half_rn(v.w * scale * gv.w));
    }
}

// ================= weight transpose -> fp16 =================
__global__ void transpose_half_kernel(const float* __restrict__ W,
                                      __half* __restrict__ T,
                                      int K, int N) {
    __shared__ float t[32][33];
    int n0 = blockIdx.x * 32, k0 = blockIdx.y * 32;
    int tx = threadIdx.x, ty = threadIdx.y;
#pragma unroll
    for (int r = 0; r < 4; r++) {
        int k = ty + r * 8;
        t[k][tx] = W[(size_t)(k0 + k) * N + n0 + tx];
    }
    __syncthreads();
#pragma unroll
    for (int r = 0; r < 4; r++) {
        int n = ty + r * 8;
        T[(size_t)(n0 + n) * K + k0 + tx] = __float2half_rn(t[tx][n]);
    }
}

// Wp transpose with gate/value interleave
__global__ void transpose_half_interleave_kernel(const float* __restrict__ W,
                                                 __half* __restrict__ T,
                                                 int K, int N) {
    __shared__ float t[32][33];
    int n0 = blockIdx.x * 32, k0 = blockIdx.y * 32;
    int tx = threadIdx.x, ty = threadIdx.y;
#pragma unroll
    for (int r = 0; r < 4; r++) {
        int k = ty + r * 8;
        t[k][tx] = W[(size_t)(k0 + k) * N + n0 + tx];
    }
    __syncthreads();
#pragma unroll
    for (int r = 0; r < 4; r++) {
        int n = ty + r * 8;
        int ncol = n0 + n;
        int rout = ((ncol & (D4 - 1)) << 1) | (ncol >> 13);
        T[(size_t)rout * K + k0 + tx] = __float2half_rn(t[tx][n]);
    }
}

// ====== fp16 GEMM: 128x128 tile, 256 thr, KC=64 (two 32-sub-blocks), 3-stage ======
// MODE 0: fp32 C = acc + bias (+R).  MODE 1: SWIGLU -> fp16 Oh[M,N/2].
// MODE 2: fp16 Oh = acc + bias.
#define TM 128
#define TN 128
#define KC 64
#define A_OFF 0
#define B_OFF 16384
#define STG_BYTES 32768
#define GEMM_SMEM (3 * STG_BYTES)

template <int MODE>
__global__ void __launch_bounds__(256, 2) gemm_f16_kernel(
    const __half* __restrict__ A, const __half* __restrict__ B,
    const float* __restrict__ bias, const float* __restrict__ R,
    float* __restrict__ C, __half* __restrict__ Oh,
    int M, int N, int K)
{
    extern __shared__ char sm[];
    const int tid = threadIdx.x;
    const int lane = tid & 31;
    const int wid = tid >> 5;
    const int wm = wid & 3;
    const int wn = wid >> 2;
    const int bm = blockIdx.x * TM;
    const int bn = blockIdx.y * TN;
    const uint32_t smb = smem_u32(sm);

    const int rowA_base = wm * 32 + (lane & 15);
    const int rowB_base = wn * 64 + (lane & 7) + ((lane >> 4) << 3);
    const uint32_t xorw = (uint32_t)((lane & 6) << 3);

    float acc[2][8][4];
#pragma unroll
    for (int i = 0; i < 2; i++)
#pragma unroll
        for (int j = 0; j < 8; j++)
#pragma unroll
            for (int q = 0; q < 4; q++) acc[i][j][q] = 0.f;

    // 2048 x 16B per chunk (A 128x64 + B 128x64), 8 per thread.
    // Each 64-wide chunk stored as two 32-wide sub-blocks (8KB each, 64B rows).
    auto issue_chunk = [&](int k0, int stg) {
        const uint32_t sbase = smb + stg * STG_BYTES;
#pragma unroll
        for (int i = 0; i < 8; i++) {
            int u = tid + (i << 8);
            const __half* src;
            uint32_t roff;
            int row;
            if (u < 1024) { row = u >> 3;          src = A + (size_t)(bm + row) * K; roff = A_OFF; }
            else          { row = (u - 1024) >> 3; src = B + (size_t)(bn + row) * K; roff = B_OFF; }
            int s8 = u & 7;
            int kh = s8 >> 2;
            int seg = s8 & 3;
            uint32_t dst = sbase + roff + (uint32_t)(kh * 8192) + (uint32_t)(row * 64) +
                           (((uint32_t)(seg * 16)) ^ ((uint32_t)((row & 6) << 3)));
            CP_ASYNC16(dst, src + k0 + kh * 32 + seg * 8);
        }
        CP_COMMIT();
    };

    const int NC = K / KC;
    issue_chunk(0, 0);
    issue_chunk(KC, 1);

    for (int c = 0; c < NC; ++c) {
        CP_WAIT1();
        __syncthreads();
        if (c + 2 < NC) issue_chunk((c + 2) * KC, (c + 2) % 3);
        else CP_COMMIT();

        const uint32_t stg = smb + (uint32_t)((c % 3) * STG_BYTES);

#pragma unroll
        for (int kh = 0; kh < 2; kh++) {
            const uint32_t sa = stg + A_OFF + (uint32_t)(kh * 8192);
            const uint32_t sb = stg + B_OFF + (uint32_t)(kh * 8192);
#pragma unroll
            for (int kk = 0; kk < 2; kk++) {
                const uint32_t cbA = ((uint32_t)(kk * 32 + ((lane >> 4) << 4))) ^ xorw;
                const uint32_t cbB = ((uint32_t)(kk * 32 + (((lane >> 3) & 1) << 4))) ^ xorw;

                uint32_t ah[2][4], b4[4][4];
#pragma unroll
                for (int mt = 0; mt < 2; mt++)
                    LDSM4(ah[mt], sa + (uint32_t)((rowA_base + mt * 16) * 64) + cbA);
#pragma unroll
                for (int bt = 0; bt < 4; bt++)
                    LDSM4(b4[bt], sb + (uint32_t)((rowB_base + bt * 16) * 64) + cbB);
#pragma unroll
                for (int mt = 0; mt < 2; mt++)
#pragma unroll
                    for (int nt = 0; nt < 8; nt++) {
                        const uint32_t* b = b4[nt >> 1];
                        if (nt & 1) MMA_F16(acc[mt][nt], ah[mt], b[2], b[3]);
                        else        MMA_F16(acc[mt][nt], ah[mt], b[0], b[1]);
                    }
            }
        }
    }

    // ---- epilogue ----
    if (MODE == 1) {
        const int outN = N >> 1;
#pragma unroll
        for (int mt = 0; mt < 2; mt++) {
            const int m = bm + wm * 32 + mt * 16 + (lane >> 2);
#pragma unroll
            for (int nt = 0; nt < 8; nt++) {
                const int nperm = bn + wn * 64 + nt * 8 + ((lane & 3) << 1);
                const int i = nperm >> 1;
                float bg = bias[i];
                float bv = bias[outN + i];
                float g0 = acc[mt][nt][0] + bg, v0 = acc[mt][nt][1] + bv;
                float g1 = acc[mt][nt][2] + bg, v1 = acc[mt][nt][3] + bv;
                float r0 = g0 / (1.f + expf(-g0)) * v0;
                float r1 = g1 / (1.f + expf(-g1)) * v1;
                Oh[(size_t)m * outN + i] = __float2half_rn(r0);
                Oh[(size_t)(m + 8) * outN + i] = __float2half_rn(r1);
            }
        }
    } else if (MODE == 2) {
#pragma unroll
        for (int mt = 0; mt < 2; mt++) {
            const int m = bm + wm * 32 + mt * 16 + (lane >> 2);
#pragma unroll
            for (int nt = 0; nt < 8; nt++) {
                const int n = bn + wn * 64 + nt * 8 + ((lane & 3) << 1);
                float2 b2 = *(const float2*)(bias + n);
                *(__half2*)(Oh + (size_t)m * N + n) = __halves2half2(
                    __float2half_rn(acc[mt][nt][0] + b2.x),
                    __float2half_rn(acc[mt][nt][1] + b2.y));
                *(__half2*)(Oh + (size_t)(m + 8) * N + n) = __halves2half2(
                    __float2half_rn(acc[mt][nt][2] + b2.x),
                    __float2half_rn(acc[mt][nt][3] + b2.y));
            }
        }
    } else {
#pragma unroll
        for (int mt = 0; mt < 2; mt++) {
            const int m = bm + wm * 32 + mt * 16 + (lane >> 2);
#pragma unroll
            for (int nt = 0; nt < 8; nt++) {
                const int n = bn + wn * 64 + nt * 8 + ((lane & 3) << 1);
                float2 b2 = *(const float2*)(bias + n);
                float2 o0, o1;
                o0.x = acc[mt][nt][0] + b2.x;
                o0.y = acc[mt][nt][1] + b2.y;
                o1.x = acc[mt][nt][2] + b2.x;
                o1.y = acc[mt][nt][3] + b2.y;
                if (R) {
                    float2 r0 = *(const float2*)(R + (size_t)m * N + n);
                    float2 r1 = *(const float2*)(R + (size_t)(m + 8) * N + n);
                    o0.x += r0.x; o0.y += r0.y;
                    o1.x += r1.x; o1.y += r1.y;
                }
                *(float2*)(C + (size_t)m * N + n) = o0;
                *(float2*)(C + (size_t)(m + 8) * N + n) = o1;
            }
        }
    }
}

// ================= RoPE: qkv fp16 -> fp16 q,k in [B,H,L,HD] =================
__global__ void rope_apply_half_kernel() {
    int idx = blockIdx.x * blockDim.x + threadIdx.x;
    if (idx >= BB * LL * HH * 64) return;
    int d = idx & 63;
    int h = (idx >> 6) & (HH - 1);
    int bl = idx >> 10;
    int b = bl >> 11;
    int l = bl & (LL - 1);
    float c = g_cos[l * 64 + d];
    float s = g_sin[l * 64 + d];
    size_t src = (size_t)bl * D3 + h * HD + d;
    size_t dst = ((size_t)(b * HH + h) * LL + l) * HD + d;

    float q1 = __half2float(g_qkvh[src]), q2 = __half2float(g_qkvh[src + 64]);
    g_qh[dst]      = __float2half_rn(q1 * c - q2 * s);
    g_qh[dst + 64] = __float2half_rn(q2 * c + q1 * s);

    size_t ks = src + DD;
    float k1 = __half2float(g_qkvh[ks]), k2 = __half2float(g_qkvh[ks + 64]);
    g_kh[dst]      = __float2half_rn(k1 * c - k2 * s);
    g_kh[dst + 64] = __float2half_rn(k2 * c + k1 * s);
}

// ================= V transpose (fp16) -> [B,H,HD,L] =================
__global__ void v_transpose_kernel() {
    __shared__ __half t[32][33];
    int l0 = blockIdx.x * 32, d0 = blockIdx.y * 32, bh = blockIdx.z;
    int b = bh >> 4, h = bh & 15;
    int tx = threadIdx.x, ty = threadIdx.y;
#pragma unroll
    for (int r = 0; r < 4; r++) {
        int l = ty + r * 8;
        t[l][tx] = g_qkvh[(size_t)(b * LL + l0 + l) * D3 + 2 * DD + h * HD + d0 + tx];
    }
    __syncthreads();
#pragma unroll
    for (int r = 0; r < 4; r++) {
        int d = ty + r * 8;
        g_vth[((size_t)bh * HD + d0 + d) * LL + l0 + tx] = t[tx][d];
    }
}

// ================= attention scores (fp16) -> fp16 g_sh =================
#define ATT_STG 16384
#define ATT_SMEM (3 * ATT_STG)

__global__ void __launch_bounds__(256, 2) attn_scores_mma_kernel() {
    extern __shared__ char sm[];
    const int jb = blockIdx.x, ib = blockIdx.y, bh = blockIdx.z;
    if (jb > ib) return;
    const int tid = threadIdx.x, lane = tid & 31, wid = tid >> 5;
    const int wm = wid & 3, wn = wid >> 2;
    const uint32_t smb = smem_u32(sm);

    const __half* Qh = g_qh + ((size_t)bh * LL + ib * 128) * HD;
    const __half* Kh = g_kh + ((size_t)bh * LL + jb * 128) * HD;

    const int rowA_base = wm * 32 + (lane & 15);
    const int rowB_base = wn * 64 + (lane & 7) + ((lane >> 4) << 3);
    const uint32_t xorw = (uint32_t)((lane & 6) << 3);

    float acc[2][8][4];
#pragma unroll
    for (int i = 0; i < 2; i++)
#pragma unroll
        for (int j = 0; j < 8; j++)
#pragma unroll
            for (int q = 0; q < 4; q++) acc[i][j][q] = 0.f;

    auto issue = [&](int c, int stg) {
        const uint32_t sb = smb + (uint32_t)(stg * ATT_STG);
        const int k0 = c * 32;
#pragma unroll
        for (int i = 0; i < 4; i++) {
            int u = tid + (i << 8);
            int row = (u >> 2) & 127;
            int seg = u & 3;
            const __half* src = (u < 512) ? Qh : Kh;
            uint32_t roff = (u < 512) ? 0u : 8192u;
            uint32_t dst = sb + roff + (uint32_t)(row * 64) +
                           (((uint32_t)(seg * 16)) ^ ((uint32_t)((row & 6) << 3)));
            CP_ASYNC16(dst, src + (size_t)row * HD + k0 + seg * 8);
        }
        CP_COMMIT();
    };

    issue(0, 0);
    issue(1, 1);
#pragma unroll 1
    for (int c = 0; c < 4; c++) {
        CP_WAIT1();
        __syncthreads();
        if (c + 2 < 4) issue(c + 2, (c + 2) % 3);
        else CP_COMMIT();
        const uint32_t stg = smb + (uint32_t)((c % 3) * ATT_STG);
#pragma unroll
        for (int kk = 0; kk < 2; kk++) {
            const uint32_t cbA = ((uint32_t)(kk * 32 + ((lane >> 4) << 4))) ^ xorw;
            const uint32_t cbB = ((uint32_t)(kk * 32 + (((lane >> 3) & 1) << 4))) ^ xorw;
            uint32_t ah[2][4], b4[4][4];
#pragma unroll
            for (int mt = 0; mt < 2; mt++)
                LDSM4(ah[mt], stg + 0 + (uint32_t)((rowA_base + mt * 16) * 64) + cbA);
#pragma unroll
            for (int bt = 0; bt < 4; bt++)
                LDSM4(b4[bt], stg + 8192 + (uint32_t)((rowB_base + bt * 16) * 64) + cbB);
#pragma unroll
            for (int mt = 0; mt < 2; mt++)
#pragma unroll
                for (int nt = 0; nt < 8; nt++) {
                    const uint32_t* b = b4[nt >> 1];
                    if (nt & 1) MMA_F16(acc[mt][nt], ah[mt], b[2], b[3]);
                    else        MMA_F16(acc[mt][nt], ah[mt], b[0], b[1]);
                }
        }
    }

    const float scale = 0.08838834764831845f;
#pragma unroll
    for (int mt = 0; mt < 2; mt++) {
        const int i0 = ib * 128 + wm * 32 + mt * 16 + (lane >> 2);
#pragma unroll
        for (int nt = 0; nt < 8; nt++) {
            const int j0 = jb * 128 + wn * 64 + nt * 8 + ((lane & 3) << 1);
            float s00 = (j0     <= i0)     ? acc[mt][nt][0] * scale : -30000.f;
            float s01 = (j0 + 1 <= i0)     ? acc[mt][nt][1] * scale : -30000.f;
            float s10 = (j0     <= i0 + 8) ? acc[mt][nt][2] * scale : -30000.f;
            float s11 = (j0 + 1 <= i0 + 8) ? acc[mt][nt][3] * scale : -30000.f;
            *(__half2*)(g_sh + ((size_t)bh * LL + i0) * LL + j0) =
                __halves2half2(__float2half_rn(s00), __float2half_rn(s01));
            *(__half2*)(g_sh + ((size_t)bh * LL + i0 + 8) * LL + j0) =
                __halves2half2(__float2half_rn(s10), __float2half_rn(s11));
        }
    }
}

// ========== row softmax (fp16 in) -> fp16 P ==========
__global__ void softmax_kernel() {
    int r = blockIdx.x;
    int i = r & (LL - 1);
    int len = ((i >> 6) + 1) << 6;
    int len2 = ((i >> 7) + 1) << 7;
    const __half* p = g_sh + (size_t)r * LL;
    __half* ph = g_ph + (size_t)r * LL;
    __shared__ float red[128];

    float m = -1e30f;
    for (int c = threadIdx.x * 4; c < len; c += 512) {
        __half2 v0 = *(const __half2*)(p + c);
        __half2 v1 = *(const __half2*)(p + c + 2);
        float a0 = __low2float(v0), a1 = __high2float(v0);
        float a2 = __low2float(v1), a3 = __high2float(v1);
        m = fmaxf(m, fmaxf(fmaxf(a0, a1), fmaxf(a2, a3)));
    }
    red[threadIdx.x] = m;
    __syncthreads();
    for (int s = 64; s > 0; s >>= 1) {
        if (threadIdx.x < s) red[threadIdx.x] = fmaxf(red[threadIdx.x], red[threadIdx.x + s]);
        __syncthreads();
    }
    m = red[0];
    __syncthreads();

    float sum = 0.f;
    for (int c = threadIdx.x * 4; c < len; c += 512) {
        __half2 v0 = *(const __half2*)(p + c);
        __half2 v1 = *(const __half2*)(p + c + 2);
        sum += expf(__low2float(v0) - m) + expf(__high2float(v0) - m)
             + expf(__low2float(v1) - m) + expf(__high2float(v1) - m);
    }
    red[threadIdx.x] = sum;
    __syncthreads();
    for (int s = 64; s > 0; s >>= 1) {
        if (threadIdx.x < s) red[threadIdx.x] += red[threadIdx.x + s];
        __syncthreads();
    }
    float inv = 1.f / red[0];
    for (int c = threadIdx.x * 4; c < len; c += 512) {
        __half2 v0 = *(const __half2*)(p + c);
        __half2 v1 = *(const __half2*)(p + c + 2);
        *(__half2*)(ph + c) = __halves2half2(
            __float2half_rn(expf(__low2float(v0) - m) * inv),
            __float2half_rn(expf(__high2float(v0) - m) * inv));
        *(__half2*)(ph + c + 2) = __halves2half2(
            __float2half_rn(expf(__low2float(v1) - m) * inv),
            __float2half_rn(expf(__high2float(v1) - m) * inv));
    }
    __half2 z = __halves2half2(__float2half_rn(0.f), __float2half_rn(0.f));
    for (int c = len + threadIdx.x * 4; c < len2; c += 512) {
        *(__half2*)(ph + c) = z;
        *(__half2*)(ph + c + 2) = z;
    }
}

// ================= O = P @ V (fp16) -> fp16 o =================
__global__ void __launch_bounds__(256, 2) attn_pv_mma_kernel() {
    extern __shared__ char sm[];
    const int ib = blockIdx.x, bh = blockIdx.y;
    const int b = bh >> 4, h = bh & 15;
    const int tid = threadIdx.x, lane = tid & 31, wid = tid >> 5;
    const int wm = wid & 3, wn = wid >> 2;
    const uint32_t smb = smem_u32(sm);

    const __half* Ph = g_ph + ((size_t)bh * LL + ib * 128) * LL;
    const __half* Vh = g_vth + (size_t)bh * HD * LL;

    const int rowA_base = wm * 32 + (lane & 15);
    const int rowB_base = wn * 64 + (lane & 7) + ((lane >> 4) << 3);
    const uint32_t xorw = (uint32_t)((lane & 6) << 3);

    float acc[2][8][4];
#pragma unroll
    for (int i = 0; i < 2; i++)
#pragma unroll
        for (int j = 0; j < 8; j++)
#pragma unroll
            for (int q = 0; q < 4; q++) acc[i][j][q] = 0.f;

    auto issue = [&](int c, int stg) {
        const uint32_t sb = smb + (uint32_t)(stg * ATT_STG);
        const int j0 = c * 32;
#pragma unroll
        for (int i = 0; i < 4; i++) {
            int u = tid + (i << 8);
            int row = (u >> 2) & 127;
            int seg = u & 3;
            const __half* src = (u < 512) ? Ph : Vh;
            uint32_t roff = (u < 512) ? 0u : 8192u;
            uint32_t dst = sb + roff + (uint32_t)(row * 64) +
                           (((uint32_t)(seg * 16)) ^ ((uint32_t)((row & 6) << 3)));
            CP_ASYNC16(dst, src + (size_t)row * LL + j0 + seg * 8);
        }
        CP_COMMIT();
    };

    const int NC = (ib + 1) * 4;
    issue(0, 0);
    issue(1, 1);
#pragma unroll 1
    for (int c = 0; c < NC; c++) {
        CP_WAIT1();
        __syncthreads();
        if (c + 2 < NC) issue(c + 2, (c + 2) % 3);
        else CP_COMMIT();
        const uint32_t stg = smb + (uint32_t)((c % 3) * ATT_STG);
#pragma unroll
        for (int kk = 0; kk < 2; kk++) {
            const uint32_t cbA = ((uint32_t)(kk * 32 + ((lane >> 4) << 4))) ^ xorw;
            const uint32_t cbB = ((uint32_t)(kk * 32 + (((lane >> 3) & 1) << 4))) ^ xorw;
            uint32_t ah[2][4], b4[4][4];
#pragma unroll
            for (int mt = 0; mt < 2; mt++)
                LDSM4(ah[mt], stg + 0 + (uint32_t)((rowA_base + mt * 16) * 64) + cbA);
#pragma unroll
            for (int bt = 0; bt < 4; bt++)
                LDSM4(b4[bt], stg + 8192 + (uint32_t)((rowB_base + bt * 16) * 64) + cbB);
#pragma unroll
            for (int mt = 0; mt < 2; mt++)
#pragma unroll
                for (int nt = 0; nt < 8; nt++) {
                    const uint32_t* bb = b4[nt >> 1];
                    if (nt & 1) MMA_F16(acc[mt][nt], ah[mt], bb[2], bb[3]);
                    else        MMA_F16(acc[mt][nt], ah[mt], bb[0], bb[1]);
                }
        }
    }

#pragma unroll
    for (int mt = 0; mt < 2; mt++) {
        const int qi = ib * 128 + wm * 32 + mt * 16 + (lane >> 2);
#pragma unroll
        for (int nt = 0; nt < 8; nt++) {
            const int d = wn * 64 + nt * 8 + ((lane & 3) << 1);
            size_t base0 = (size_t)(b * LL + qi) * DD + h * HD + d;
            size_t base1 = (size_t)(b * LL + qi + 8) * DD + h * HD + d;
            *(__half2*)(g_ah + base0) = __halves2half2(
                __float2half_rn(acc[mt][nt][0]), __float2half_rn(acc[mt][nt][1]));
            *(__half2*)(g_ah + base1) = __halves2half2(
                __float2half_rn(acc[mt][nt][2]), __float2half_rn(acc[mt][nt][3]));
        }
    }
}

// ================= launch =================
extern "C" void kernel_launch(void* const* d_in, const int* in_sizes, int n_in,
                              void* d_out, int out_size) {
    const float* x    = (const float*)d_in[0];
    const float* Wqkv = (const float*)d_in[1];
    const float* bqkv = (const float*)d_in[2];
    const float* Wo   = (const float*)d_in[3];
    const float* bo   = (const float*)d_in[4];
    const float* g1   = (const float*)d_in[5];
    const float* g2   = (const float*)d_in[6];
    const float* Wp   = (const float*)d_in[7];
    const float* bp   = (const float*)d_in[8];
    const float* Wff  = (const float*)d_in[9];
    const float* bff  = (const float*)d_in[10];
    float* out = (float*)d_out;

    __half *ah, *fh, *wq, *wo, *wp, *wf, *qkvh;
    float *x1;
    cudaGetSymbolAddress((void**)&ah,   g_ah);
    cudaGetSymbolAddress((void**)&fh,   g_fh);
    cudaGetSymbolAddress((void**)&wq,   g_WqkvT);
    cudaGetSymbolAddress((void**)&wo,   g_WoT);
    cudaGetSymbolAddress((void**)&wp,   g_WpT);
    cudaGetSymbolAddress((void**)&wf,   g_WffT);
    cudaGetSymbolAddress((void**)&qkvh, g_qkvh);
    cudaGetSymbolAddress((void**)&x1,   g_x1);

    cudaFuncSetAttribute(gemm_f16_kernel<0>,
                         cudaFuncAttributeMaxDynamicSharedMemorySize, GEMM_SMEM);
    cudaFuncSetAttribute(gemm_f16_kernel<1>,
                         cudaFuncAttributeMaxDynamicSharedMemorySize, GEMM_SMEM);
    cudaFuncSetAttribute(gemm_f16_kernel<2>,
                         cudaFuncAttributeMaxDynamicSharedMemorySize, GEMM_SMEM);
    cudaFuncSetAttribute(attn_scores_mma_kernel,
                         cudaFuncAttributeMaxDynamicSharedMemorySize, ATT_SMEM);
    cudaFuncSetAttribute(attn_pv_mma_kernel,
                         cudaFuncAttributeMaxDynamicSharedMemorySize, ATT_SMEM);

    dim3 tb(32, 8);

    rope_table_kernel<<<LL, 64>>>();
    transpose_half_kernel<<<dim3(D3 / 32, DD / 32), tb>>>(Wqkv, wq, DD, D3);
    rmsnorm_half_kernel<<<MROWS, 256>>>(x, g1, ah);

    // qkv (fp16 out) = h @ Wqkv + bqkv   (launch #4 — profiled)
    gemm_f16_kernel<2><<<dim3(MROWS / TM, D3 / TN), 256, GEMM_SMEM>>>(
        ah, wq, bqkv, nullptr, nullptr, qkvh, MROWS, D3, DD);

    {
        int total = BB * LL * HH * 64;
        rope_apply_half_kernel<<<(total + 255) / 256, 256>>>();
    }
    v_transpose_kernel<<<dim3(LL / 32, HD / 32, BB * HH), tb>>>();
    attn_scores_mma_kernel<<<dim3(LL / 128, LL / 128, BB * HH), 256, ATT_SMEM>>>();
    softmax_kernel<<<BB * HH * LL, 128>>>();
    attn_pv_mma_kernel<<<dim3(LL / 128, BB * HH), 256, ATT_SMEM>>>();

    transpose_half_kernel<<<dim3(DD / 32, DD / 32), tb>>>(Wo, wo, DD, DD);
    gemm_f16_kernel<0><<<dim3(MROWS / TM, DD / TN), 256, GEMM_SMEM>>>(
        ah, wo, bo, x, x1, nullptr, MROWS, DD, DD);

    rmsnorm_half_kernel<<<MROWS, 256>>>(x1, g2, ah);

    transpose_half_interleave_kernel<<<dim3(D8 / 32, DD / 32), tb>>>(Wp, wp, DD, D8);
    gemm_f16_kernel<1><<<dim3(MROWS / TM, D8 / TN), 256, GEMM_SMEM>>>(
        ah, wp, bp, nullptr, nullptr, fh, MROWS, D8, DD);

    transpose_half_kernel<<<dim3(DD / 32, D4 / 32), tb>>>(Wff, wf, D4, DD);
    gemm_f16_kernel<0><<<dim3(MROWS / TM, DD / TN), 256, GEMM_SMEM>>>(
        fh, wf, bff, x1, out, nullptr, MROWS, DD, D4);
}